// round 1
// baseline (speedup 1.0000x reference)
#include <cuda_runtime.h>
#include <math.h>

#define Bb 4
#define Tt 2048
#define Cc 1024
#define Hh 16
#define Dd 64

// Scratch (allocation-free rule: device globals)
__device__ float g_qkv[(size_t)Bb * Tt * 3 * Cc];  // 25.2M floats
__device__ float g_y[(size_t)Bb * Tt * Cc];        // 8.4M floats

// ---------------------------------------------------------------------------
// SGEMM + bias: C[M,N] = A[M,K] @ B[K,N] + bias[N]
// BM=BN=64, BK=16, 256 threads, 4x4 microtile per thread.
// ---------------------------------------------------------------------------
__global__ __launch_bounds__(256) void sgemm_bias_kernel(
    const float* __restrict__ A, const float* __restrict__ B,
    const float* __restrict__ bias, float* __restrict__ C,
    int M, int N, int K)
{
    const int BM = 64, BN = 64, BK = 16;
    __shared__ float As[BK][BM];   // transposed A tile
    __shared__ float Bs[BK][BN];

    const int tid = threadIdx.x;
    const int bm = blockIdx.y * BM;
    const int bn = blockIdx.x * BN;
    const int tx = tid & 15, ty = tid >> 4;

    const int arow = tid >> 2,  acol = (tid & 3)  << 2;  // A tile [64][16]
    const int brow = tid >> 4,  bcol = (tid & 15) << 2;  // B tile [16][64]

    const float* Aptr = A + (size_t)(bm + arow) * K + acol;
    const float* Bptr = B + (size_t)brow * N + bn + bcol;

    float acc[4][4];
    #pragma unroll
    for (int i = 0; i < 4; i++)
        #pragma unroll
        for (int j = 0; j < 4; j++) acc[i][j] = 0.f;

    for (int k0 = 0; k0 < K; k0 += BK) {
        float4 a4 = *(const float4*)(Aptr + k0);
        As[acol + 0][arow] = a4.x;
        As[acol + 1][arow] = a4.y;
        As[acol + 2][arow] = a4.z;
        As[acol + 3][arow] = a4.w;
        float4 b4 = *(const float4*)(Bptr + (size_t)k0 * N);
        *(float4*)&Bs[brow][bcol] = b4;
        __syncthreads();

        #pragma unroll
        for (int kk = 0; kk < BK; kk++) {
            float4 av = *(const float4*)&As[kk][ty << 2];
            float4 bv = *(const float4*)&Bs[kk][tx << 2];
            float a0 = av.x, a1 = av.y, a2 = av.z, a3 = av.w;
            float b0 = bv.x, b1 = bv.y, b2 = bv.z, b3 = bv.w;
            acc[0][0] += a0 * b0; acc[0][1] += a0 * b1; acc[0][2] += a0 * b2; acc[0][3] += a0 * b3;
            acc[1][0] += a1 * b0; acc[1][1] += a1 * b1; acc[1][2] += a1 * b2; acc[1][3] += a1 * b3;
            acc[2][0] += a2 * b0; acc[2][1] += a2 * b1; acc[2][2] += a2 * b2; acc[2][3] += a2 * b3;
            acc[3][0] += a3 * b0; acc[3][1] += a3 * b1; acc[3][2] += a3 * b2; acc[3][3] += a3 * b3;
        }
        __syncthreads();
    }

    #pragma unroll
    for (int i = 0; i < 4; i++) {
        int r = bm + (ty << 2) + i;
        #pragma unroll
        for (int j = 0; j < 4; j++) {
            int c = bn + (tx << 2) + j;
            C[(size_t)r * N + c] = acc[i][j] + bias[c];
        }
    }
}

// ---------------------------------------------------------------------------
// Flash attention (causal, online softmax), fp32.
// Grid: (T/64, H, B). Block: 128 threads. Each thread: 4 rows x 8 cols
// microtile of S and of O. K smem buffer reused for P after S is computed.
// Smem: 3 x 64 x 65 floats = 49920 bytes (dynamic).
// ---------------------------------------------------------------------------
__global__ __launch_bounds__(128) void flash_kernel(
    const float* __restrict__ qkv, float* __restrict__ y)
{
    extern __shared__ float sm[];
    float (*Qs)[65] = (float(*)[65])sm;                  // Q tile
    float (*KP)[65] = (float(*)[65])(sm + 64 * 65);      // K tile, reused as P
    float (*Vs)[65] = (float(*)[65])(sm + 2 * 64 * 65);  // V tile

    const int qb = blockIdx.x, h = blockIdx.y, b = blockIdx.z;
    const int tid = threadIdx.x;
    const int tx = tid & 7;      // 0..7  -> 8 cols each
    const int ty = tid >> 3;     // 0..15 -> 4 rows each

    const size_t rs = (size_t)3 * Cc;  // 3072 row stride in qkv
    const float* qbase = qkv + ((size_t)(b * Tt) + (size_t)qb * 64) * rs + h * Dd;

    // Load Q tile (64x64), float4-coalesced
    #pragma unroll
    for (int it = 0; it < 8; it++) {
        int idx = tid + 128 * it;
        int r = idx >> 4, c = (idx & 15) << 2;
        float4 v = *(const float4*)(qbase + (size_t)r * rs + c);
        Qs[r][c + 0] = v.x; Qs[r][c + 1] = v.y;
        Qs[r][c + 2] = v.z; Qs[r][c + 3] = v.w;
    }

    float o[4][8];
    float mrow[4], lrow[4];
    #pragma unroll
    for (int i = 0; i < 4; i++) {
        mrow[i] = -INFINITY; lrow[i] = 0.f;
        #pragma unroll
        for (int j = 0; j < 8; j++) o[i][j] = 0.f;
    }

    const float scale = 0.125f;  // 1/sqrt(64)

    for (int kb = 0; kb <= qb; kb++) {
        __syncthreads();  // previous P/V consumption complete (also covers Q load)

        const float* kbase = qkv + ((size_t)(b * Tt) + (size_t)kb * 64) * rs + Cc + h * Dd;
        const float* vbase = kbase + Cc;
        #pragma unroll
        for (int it = 0; it < 8; it++) {
            int idx = tid + 128 * it;
            int r = idx >> 4, c = (idx & 15) << 2;
            float4 kv = *(const float4*)(kbase + (size_t)r * rs + c);
            KP[r][c + 0] = kv.x; KP[r][c + 1] = kv.y;
            KP[r][c + 2] = kv.z; KP[r][c + 3] = kv.w;
            float4 vv = *(const float4*)(vbase + (size_t)r * rs + c);
            Vs[r][c + 0] = vv.x; Vs[r][c + 1] = vv.y;
            Vs[r][c + 2] = vv.z; Vs[r][c + 3] = vv.w;
        }
        __syncthreads();

        // S = Q K^T (4x8 per thread)
        float s[4][8];
        #pragma unroll
        for (int i = 0; i < 4; i++)
            #pragma unroll
            for (int j = 0; j < 8; j++) s[i][j] = 0.f;

        #pragma unroll 8
        for (int d = 0; d < 64; d++) {
            float qv[4], kv[8];
            #pragma unroll
            for (int i = 0; i < 4; i++) qv[i] = Qs[(ty << 2) + i][d];
            #pragma unroll
            for (int j = 0; j < 8; j++) kv[j] = KP[(tx << 3) + j][d];
            #pragma unroll
            for (int i = 0; i < 4; i++)
                #pragma unroll
                for (int j = 0; j < 8; j++) s[i][j] += qv[i] * kv[j];
        }

        // Scale + causal mask (only diagonal tile needs masking)
        if (kb == qb) {
            #pragma unroll
            for (int i = 0; i < 4; i++) {
                int qg = (ty << 2) + i;
                #pragma unroll
                for (int j = 0; j < 8; j++) {
                    int kg = (tx << 3) + j;
                    s[i][j] = (kg <= qg) ? s[i][j] * scale : -INFINITY;
                }
            }
        } else {
            #pragma unroll
            for (int i = 0; i < 4; i++)
                #pragma unroll
                for (int j = 0; j < 8; j++) s[i][j] *= scale;
        }

        // Online softmax (row reduction across tx group = lanes xor 1,2,4)
        #pragma unroll
        for (int i = 0; i < 4; i++) {
            float mx = s[i][0];
            #pragma unroll
            for (int j = 1; j < 8; j++) mx = fmaxf(mx, s[i][j]);
            mx = fmaxf(mx, __shfl_xor_sync(0xffffffffu, mx, 1));
            mx = fmaxf(mx, __shfl_xor_sync(0xffffffffu, mx, 2));
            mx = fmaxf(mx, __shfl_xor_sync(0xffffffffu, mx, 4));
            float mn = fmaxf(mrow[i], mx);
            float alpha = __expf(mrow[i] - mn);
            mrow[i] = mn;
            float rsum = 0.f;
            #pragma unroll
            for (int j = 0; j < 8; j++) {
                s[i][j] = __expf(s[i][j] - mn);
                rsum += s[i][j];
            }
            rsum += __shfl_xor_sync(0xffffffffu, rsum, 1);
            rsum += __shfl_xor_sync(0xffffffffu, rsum, 2);
            rsum += __shfl_xor_sync(0xffffffffu, rsum, 4);
            lrow[i] = lrow[i] * alpha + rsum;
            #pragma unroll
            for (int j = 0; j < 8; j++) o[i][j] *= alpha;
        }

        __syncthreads();  // everyone done reading K from KP
        #pragma unroll
        for (int i = 0; i < 4; i++)
            #pragma unroll
            for (int j = 0; j < 8; j++)
                KP[(ty << 2) + i][(tx << 3) + j] = s[i][j];
        __syncthreads();

        // O += P @ V
        #pragma unroll 8
        for (int c = 0; c < 64; c++) {
            float pv[4], vv[8];
            #pragma unroll
            for (int i = 0; i < 4; i++) pv[i] = KP[(ty << 2) + i][c];
            #pragma unroll
            for (int j = 0; j < 8; j++) vv[j] = Vs[c][(tx << 3) + j];
            #pragma unroll
            for (int i = 0; i < 4; i++)
                #pragma unroll
                for (int j = 0; j < 8; j++) o[i][j] += pv[i] * vv[j];
        }
    }

    // Normalize and write y[b, t, h*64 + d]
    #pragma unroll
    for (int i = 0; i < 4; i++) {
        float inv = 1.f / lrow[i];
        int r = qb * 64 + (ty << 2) + i;
        float* yrow = y + ((size_t)(b * Tt) + r) * Cc + h * Dd + (tx << 3);
        #pragma unroll
        for (int j = 0; j < 8; j++) yrow[j] = o[i][j] * inv;
    }
}

// ---------------------------------------------------------------------------
extern "C" void kernel_launch(void* const* d_in, const int* in_sizes, int n_in,
                              void* d_out, int out_size)
{
    const float* x  = (const float*)d_in[0];
    const float* Wa = (const float*)d_in[1];
    const float* ba = (const float*)d_in[2];
    const float* Wp = (const float*)d_in[3];
    const float* bp = (const float*)d_in[4];
    float* out = (float*)d_out;

    float *qkv, *y;
    cudaGetSymbolAddress((void**)&qkv, g_qkv);
    cudaGetSymbolAddress((void**)&y,   g_y);

    const int M = Bb * Tt;           // 8192
    const int N1 = 3 * Cc;           // 3072

    // GEMM1: qkv = x @ W_attn + b_attn
    sgemm_bias_kernel<<<dim3(N1 / 64, M / 64), 256>>>(x, Wa, ba, qkv, M, N1, Cc);

    // Flash attention
    const int smem_bytes = 3 * 64 * 65 * (int)sizeof(float);  // 49920
    cudaFuncSetAttribute(flash_kernel, cudaFuncAttributeMaxDynamicSharedMemorySize, smem_bytes);
    flash_kernel<<<dim3(Tt / 64, Hh, Bb), 128, smem_bytes>>>(qkv, y);

    // GEMM2: out = y @ W_proj + b_proj
    sgemm_bias_kernel<<<dim3(Cc / 64, M / 64), 256>>>(y, Wp, bp, out, M, Cc, Cc);
}

// round 3
// speedup vs baseline: 1.5651x; 1.5651x over previous
#include <cuda_runtime.h>
#include <cstdint>
#include <math.h>

#define Bb 4
#define Tt 2048
#define Cc 1024
#define Hh 16
#define Dd 64

// Scratch (allocation-free rule: device globals)
__device__ float g_qkv[(size_t)Bb * Tt * 3 * Cc];  // 25.2M floats
__device__ float g_y[(size_t)Bb * Tt * Cc];        // 8.4M floats

// ---------------------------------------------------------------------------
// Helpers: tf32 convert, mma.sync, cp.async
// ---------------------------------------------------------------------------
__device__ __forceinline__ uint32_t f2tf32(float f) {
    uint32_t r;
    asm("cvt.rna.tf32.f32 %0, %1;" : "=r"(r) : "f"(f));
    return r;
}

__device__ __forceinline__ void mma_tf32(float c[4], const uint32_t a[4], const uint32_t b[2]) {
    asm volatile(
        "mma.sync.aligned.m16n8k8.row.col.f32.tf32.tf32.f32 "
        "{%0,%1,%2,%3}, {%4,%5,%6,%7}, {%8,%9}, {%0,%1,%2,%3};\n"
        : "+f"(c[0]), "+f"(c[1]), "+f"(c[2]), "+f"(c[3])
        : "r"(a[0]), "r"(a[1]), "r"(a[2]), "r"(a[3]), "r"(b[0]), "r"(b[1]));
}

__device__ __forceinline__ void cp_async16(void* smem_dst, const void* gmem_src) {
    uint32_t s = (uint32_t)__cvta_generic_to_shared(smem_dst);
    asm volatile("cp.async.cg.shared.global [%0], [%1], 16;\n" :: "r"(s), "l"(gmem_src));
}
#define CP_COMMIT() asm volatile("cp.async.commit_group;\n" ::: "memory")
#define CP_WAIT(n)  asm volatile("cp.async.wait_group %0;\n" :: "n"(n) : "memory")

// ---------------------------------------------------------------------------
// TF32 tensor-core GEMM + bias: C[M,N] = A[M,K] @ B[K,N] + bias[N]
// BM=128, BN=128, BK=32. 256 threads = 8 warps (2m x 4n), warp tile 64x32.
// Smem: A [128][36] (pad 4), B [32][136] (pad 8)  -> conflict-free frags.
// Double-buffered cp.async pipeline.
// ---------------------------------------------------------------------------
#define AS_STRIDE 36
#define BS_STRIDE 136
#define A_TILE_FLOATS (128 * AS_STRIDE)  // 4608
#define B_TILE_FLOATS (32 * BS_STRIDE)   // 4352

__global__ __launch_bounds__(256) void tf32_gemm_bias_kernel(
    const float* __restrict__ A, const float* __restrict__ B,
    const float* __restrict__ bias, float* __restrict__ C,
    int M, int N, int K)
{
    extern __shared__ float sm[];
    float* As[2] = { sm, sm + A_TILE_FLOATS };
    float* Bs[2] = { sm + 2 * A_TILE_FLOATS, sm + 2 * A_TILE_FLOATS + B_TILE_FLOATS };

    const int tid  = threadIdx.x;
    const int lane = tid & 31, wid = tid >> 5;
    const int warp_m = wid >> 2;   // 0..1
    const int warp_n = wid & 3;    // 0..3
    const int gid = lane >> 2;     // 0..7
    const int tg  = lane & 3;      // 0..3

    const int bm = blockIdx.y * 128;
    const int bn = blockIdx.x * 128;

    // gmem->smem load coordinates
    const int a_row = tid >> 3;          // 0..31 (4 passes of +32)
    const int a_col = (tid & 7) << 2;    // 0,4,...,28
    const int b_r0 = tid >> 5;           // 0..7 (4 passes of +8)
    const int b_c0 = (tid & 31) << 2;

    const int ktiles = K >> 5;  // K/32

    auto load_tile = [&](int buf, int kt) {
        const float* Ag = A + (size_t)(bm) * K + kt * 32;
        #pragma unroll
        for (int p = 0; p < 4; p++) {
            int r = a_row + 32 * p;
            cp_async16(&As[buf][r * AS_STRIDE + a_col], Ag + (size_t)r * K + a_col);
        }
        const float* Bg = B + (size_t)(kt * 32) * N + bn;
        #pragma unroll
        for (int p = 0; p < 4; p++) {
            int r = b_r0 + 8 * p;
            cp_async16(&Bs[buf][r * BS_STRIDE + b_c0], Bg + (size_t)r * N + b_c0);
        }
    };

    float acc[4][4][4];
    #pragma unroll
    for (int mt = 0; mt < 4; mt++)
        #pragma unroll
        for (int nt = 0; nt < 4; nt++)
            #pragma unroll
            for (int r = 0; r < 4; r++) acc[mt][nt][r] = 0.f;

    load_tile(0, 0);
    CP_COMMIT();

    for (int kt = 0; kt < ktiles; kt++) {
        const int cur = kt & 1;
        if (kt + 1 < ktiles) {
            load_tile(cur ^ 1, kt + 1);
            CP_COMMIT();
            CP_WAIT(1);
        } else {
            CP_WAIT(0);
        }
        __syncthreads();

        const float* as = As[cur];
        const float* bs = Bs[cur];

        #pragma unroll
        for (int ks = 0; ks < 4; ks++) {
            const int k8 = ks << 3;
            uint32_t af[4][4];
            #pragma unroll
            for (int mt = 0; mt < 4; mt++) {
                int r0 = warp_m * 64 + mt * 16 + gid;
                af[mt][0] = f2tf32(as[(r0    ) * AS_STRIDE + k8 + tg    ]);
                af[mt][1] = f2tf32(as[(r0 + 8) * AS_STRIDE + k8 + tg    ]);
                af[mt][2] = f2tf32(as[(r0    ) * AS_STRIDE + k8 + tg + 4]);
                af[mt][3] = f2tf32(as[(r0 + 8) * AS_STRIDE + k8 + tg + 4]);
            }
            uint32_t bf[4][2];
            #pragma unroll
            for (int nt = 0; nt < 4; nt++) {
                int c = warp_n * 32 + nt * 8 + gid;
                bf[nt][0] = f2tf32(bs[(k8 + tg    ) * BS_STRIDE + c]);
                bf[nt][1] = f2tf32(bs[(k8 + tg + 4) * BS_STRIDE + c]);
            }
            #pragma unroll
            for (int mt = 0; mt < 4; mt++)
                #pragma unroll
                for (int nt = 0; nt < 4; nt++)
                    mma_tf32(acc[mt][nt], af[mt], bf[nt]);
        }
        __syncthreads();
    }

    // Epilogue: add bias, write fp32
    #pragma unroll
    for (int mt = 0; mt < 4; mt++) {
        #pragma unroll
        for (int nt = 0; nt < 4; nt++) {
            int r = bm + warp_m * 64 + mt * 16 + gid;
            int c = bn + warp_n * 32 + nt * 8 + (tg << 1);
            float b0 = bias[c], b1 = bias[c + 1];
            float2 v0 = make_float2(acc[mt][nt][0] + b0, acc[mt][nt][1] + b1);
            float2 v1 = make_float2(acc[mt][nt][2] + b0, acc[mt][nt][3] + b1);
            *(float2*)(C + (size_t)r * N + c)       = v0;
            *(float2*)(C + (size_t)(r + 8) * N + c) = v1;
        }
    }
}

// ---------------------------------------------------------------------------
// Flash attention (causal, online softmax), fp32.
// ---------------------------------------------------------------------------
__global__ __launch_bounds__(128) void flash_kernel(
    const float* __restrict__ qkv, float* __restrict__ y)
{
    extern __shared__ float sm[];
    float (*Qs)[65] = (float(*)[65])sm;
    float (*KP)[65] = (float(*)[65])(sm + 64 * 65);
    float (*Vs)[65] = (float(*)[65])(sm + 2 * 64 * 65);

    const int qb = blockIdx.x, h = blockIdx.y, b = blockIdx.z;
    const int tid = threadIdx.x;
    const int tx = tid & 7;
    const int ty = tid >> 3;

    const size_t rs = (size_t)3 * Cc;
    const float* qbase = qkv + ((size_t)(b * Tt) + (size_t)qb * 64) * rs + h * Dd;

    #pragma unroll
    for (int it = 0; it < 8; it++) {
        int idx = tid + 128 * it;
        int r = idx >> 4, c = (idx & 15) << 2;
        float4 v = *(const float4*)(qbase + (size_t)r * rs + c);
        Qs[r][c + 0] = v.x; Qs[r][c + 1] = v.y;
        Qs[r][c + 2] = v.z; Qs[r][c + 3] = v.w;
    }

    float o[4][8];
    float mrow[4], lrow[4];
    #pragma unroll
    for (int i = 0; i < 4; i++) {
        mrow[i] = -INFINITY; lrow[i] = 0.f;
        #pragma unroll
        for (int j = 0; j < 8; j++) o[i][j] = 0.f;
    }

    const float scale = 0.125f;

    for (int kb = 0; kb <= qb; kb++) {
        __syncthreads();

        const float* kbase = qkv + ((size_t)(b * Tt) + (size_t)kb * 64) * rs + Cc + h * Dd;
        const float* vbase = kbase + Cc;
        #pragma unroll
        for (int it = 0; it < 8; it++) {
            int idx = tid + 128 * it;
            int r = idx >> 4, c = (idx & 15) << 2;
            float4 kv = *(const float4*)(kbase + (size_t)r * rs + c);
            KP[r][c + 0] = kv.x; KP[r][c + 1] = kv.y;
            KP[r][c + 2] = kv.z; KP[r][c + 3] = kv.w;
            float4 vv = *(const float4*)(vbase + (size_t)r * rs + c);
            Vs[r][c + 0] = vv.x; Vs[r][c + 1] = vv.y;
            Vs[r][c + 2] = vv.z; Vs[r][c + 3] = vv.w;
        }
        __syncthreads();

        float s[4][8];
        #pragma unroll
        for (int i = 0; i < 4; i++)
            #pragma unroll
            for (int j = 0; j < 8; j++) s[i][j] = 0.f;

        #pragma unroll 8
        for (int d = 0; d < 64; d++) {
            float qv[4], kv[8];
            #pragma unroll
            for (int i = 0; i < 4; i++) qv[i] = Qs[(ty << 2) + i][d];
            #pragma unroll
            for (int j = 0; j < 8; j++) kv[j] = KP[(tx << 3) + j][d];
            #pragma unroll
            for (int i = 0; i < 4; i++)
                #pragma unroll
                for (int j = 0; j < 8; j++) s[i][j] += qv[i] * kv[j];
        }

        if (kb == qb) {
            #pragma unroll
            for (int i = 0; i < 4; i++) {
                int qg = (ty << 2) + i;
                #pragma unroll
                for (int j = 0; j < 8; j++) {
                    int kg = (tx << 3) + j;
                    s[i][j] = (kg <= qg) ? s[i][j] * scale : -INFINITY;
                }
            }
        } else {
            #pragma unroll
            for (int i = 0; i < 4; i++)
                #pragma unroll
                for (int j = 0; j < 8; j++) s[i][j] *= scale;
        }

        #pragma unroll
        for (int i = 0; i < 4; i++) {
            float mx = s[i][0];
            #pragma unroll
            for (int j = 1; j < 8; j++) mx = fmaxf(mx, s[i][j]);
            mx = fmaxf(mx, __shfl_xor_sync(0xffffffffu, mx, 1));
            mx = fmaxf(mx, __shfl_xor_sync(0xffffffffu, mx, 2));
            mx = fmaxf(mx, __shfl_xor_sync(0xffffffffu, mx, 4));
            float mn = fmaxf(mrow[i], mx);
            float alpha = __expf(mrow[i] - mn);
            mrow[i] = mn;
            float rsum = 0.f;
            #pragma unroll
            for (int j = 0; j < 8; j++) {
                s[i][j] = __expf(s[i][j] - mn);
                rsum += s[i][j];
            }
            rsum += __shfl_xor_sync(0xffffffffu, rsum, 1);
            rsum += __shfl_xor_sync(0xffffffffu, rsum, 2);
            rsum += __shfl_xor_sync(0xffffffffu, rsum, 4);
            lrow[i] = lrow[i] * alpha + rsum;
            #pragma unroll
            for (int j = 0; j < 8; j++) o[i][j] *= alpha;
        }

        __syncthreads();
        #pragma unroll
        for (int i = 0; i < 4; i++)
            #pragma unroll
            for (int j = 0; j < 8; j++)
                KP[(ty << 2) + i][(tx << 3) + j] = s[i][j];
        __syncthreads();

        #pragma unroll 8
        for (int c = 0; c < 64; c++) {
            float pv[4], vv[8];
            #pragma unroll
            for (int i = 0; i < 4; i++) pv[i] = KP[(ty << 2) + i][c];
            #pragma unroll
            for (int j = 0; j < 8; j++) vv[j] = Vs[c][(tx << 3) + j];
            #pragma unroll
            for (int i = 0; i < 4; i++)
                #pragma unroll
                for (int j = 0; j < 8; j++) o[i][j] += pv[i] * vv[j];
        }
    }

    #pragma unroll
    for (int i = 0; i < 4; i++) {
        float inv = 1.f / lrow[i];
        int r = qb * 64 + (ty << 2) + i;
        float* yrow = y + ((size_t)(b * Tt) + r) * Cc + h * Dd + (tx << 3);
        #pragma unroll
        for (int j = 0; j < 8; j++) yrow[j] = o[i][j] * inv;
    }
}

// ---------------------------------------------------------------------------
extern "C" void kernel_launch(void* const* d_in, const int* in_sizes, int n_in,
                              void* d_out, int out_size)
{
    const float* x  = (const float*)d_in[0];
    const float* Wa = (const float*)d_in[1];
    const float* ba = (const float*)d_in[2];
    const float* Wp = (const float*)d_in[3];
    const float* bp = (const float*)d_in[4];
    float* out = (float*)d_out;

    float *qkv, *y;
    cudaGetSymbolAddress((void**)&qkv, g_qkv);
    cudaGetSymbolAddress((void**)&y,   g_y);

    const int M = Bb * Tt;           // 8192
    const int N1 = 3 * Cc;           // 3072

    const int gemm_smem = (2 * A_TILE_FLOATS + 2 * B_TILE_FLOATS) * (int)sizeof(float); // 71680
    static int attr_set = 0;
    if (!attr_set) {
        cudaFuncSetAttribute(tf32_gemm_bias_kernel, cudaFuncAttributeMaxDynamicSharedMemorySize, gemm_smem);
        cudaFuncSetAttribute(flash_kernel, cudaFuncAttributeMaxDynamicSharedMemorySize, 3 * 64 * 65 * (int)sizeof(float));
        attr_set = 1;
    }

    // GEMM1: qkv = x @ W_attn + b_attn
    tf32_gemm_bias_kernel<<<dim3(N1 / 128, M / 128), 256, gemm_smem>>>(x, Wa, ba, qkv, M, N1, Cc);

    // Flash attention
    const int smem_bytes = 3 * 64 * 65 * (int)sizeof(float);
    flash_kernel<<<dim3(Tt / 64, Hh, Bb), 128, smem_bytes>>>(qkv, y);

    // GEMM2: out = y @ W_proj + b_proj
    tf32_gemm_bias_kernel<<<dim3(Cc / 128, M / 128), 256, gemm_smem>>>(y, Wp, bp, out, M, Cc, Cc);
}

// round 4
// speedup vs baseline: 1.5807x; 1.0099x over previous
#include <cuda_runtime.h>
#include <cstdint>
#include <math.h>

#define Bb 4
#define Tt 2048
#define Cc 1024
#define Hh 16
#define Dd 64

// Scratch (allocation-free rule: device globals)
__device__ float g_qkv[(size_t)Bb * Tt * 3 * Cc];  // 25.2M floats
__device__ float g_y[(size_t)Bb * Tt * Cc];        // 8.4M floats

// ---------------------------------------------------------------------------
// Helpers: tf32 convert, mma.sync, cp.async
// ---------------------------------------------------------------------------
__device__ __forceinline__ uint32_t f2tf32(float f) {
    uint32_t r;
    asm("cvt.rna.tf32.f32 %0, %1;" : "=r"(r) : "f"(f));
    return r;
}

__device__ __forceinline__ void mma_tf32(float c[4], const uint32_t a[4], const uint32_t b[2]) {
    asm volatile(
        "mma.sync.aligned.m16n8k8.row.col.f32.tf32.tf32.f32 "
        "{%0,%1,%2,%3}, {%4,%5,%6,%7}, {%8,%9}, {%0,%1,%2,%3};\n"
        : "+f"(c[0]), "+f"(c[1]), "+f"(c[2]), "+f"(c[3])
        : "r"(a[0]), "r"(a[1]), "r"(a[2]), "r"(a[3]), "r"(b[0]), "r"(b[1]));
}

__device__ __forceinline__ void cp_async16(void* smem_dst, const void* gmem_src) {
    uint32_t s = (uint32_t)__cvta_generic_to_shared(smem_dst);
    asm volatile("cp.async.cg.shared.global [%0], [%1], 16;\n" :: "r"(s), "l"(gmem_src));
}
#define CP_COMMIT() asm volatile("cp.async.commit_group;\n" ::: "memory")
#define CP_WAIT(n)  asm volatile("cp.async.wait_group %0;\n" :: "n"(n) : "memory")

// ---------------------------------------------------------------------------
// TF32 tensor-core GEMM + bias: C[M,N] = A[M,K] @ B[K,N] + bias[N]
// BM=128, BN=128, BK=32. 256 threads = 8 warps (2m x 4n), warp tile 64x32.
// Smem: A [128][36] (pad 4), B [32][136] (pad 8)  -> conflict-free frags.
// Double-buffered cp.async pipeline.
// ---------------------------------------------------------------------------
#define AS_STRIDE 36
#define BS_STRIDE 136
#define A_TILE_FLOATS (128 * AS_STRIDE)  // 4608
#define B_TILE_FLOATS (32 * BS_STRIDE)   // 4352

__global__ __launch_bounds__(256) void tf32_gemm_bias_kernel(
    const float* __restrict__ A, const float* __restrict__ B,
    const float* __restrict__ bias, float* __restrict__ C,
    int M, int N, int K)
{
    extern __shared__ float sm[];
    float* As[2] = { sm, sm + A_TILE_FLOATS };
    float* Bs[2] = { sm + 2 * A_TILE_FLOATS, sm + 2 * A_TILE_FLOATS + B_TILE_FLOATS };

    const int tid  = threadIdx.x;
    const int lane = tid & 31, wid = tid >> 5;
    const int warp_m = wid >> 2;   // 0..1
    const int warp_n = wid & 3;    // 0..3
    const int gid = lane >> 2;     // 0..7
    const int tg  = lane & 3;      // 0..3

    const int bm = blockIdx.y * 128;
    const int bn = blockIdx.x * 128;

    // gmem->smem load coordinates
    const int a_row = tid >> 3;          // 0..31 (4 passes of +32)
    const int a_col = (tid & 7) << 2;    // 0,4,...,28
    const int b_r0 = tid >> 5;           // 0..7 (4 passes of +8)
    const int b_c0 = (tid & 31) << 2;

    const int ktiles = K >> 5;  // K/32

    auto load_tile = [&](int buf, int kt) {
        const float* Ag = A + (size_t)(bm) * K + kt * 32;
        #pragma unroll
        for (int p = 0; p < 4; p++) {
            int r = a_row + 32 * p;
            cp_async16(&As[buf][r * AS_STRIDE + a_col], Ag + (size_t)r * K + a_col);
        }
        const float* Bg = B + (size_t)(kt * 32) * N + bn;
        #pragma unroll
        for (int p = 0; p < 4; p++) {
            int r = b_r0 + 8 * p;
            cp_async16(&Bs[buf][r * BS_STRIDE + b_c0], Bg + (size_t)r * N + b_c0);
        }
    };

    float acc[4][4][4];
    #pragma unroll
    for (int mt = 0; mt < 4; mt++)
        #pragma unroll
        for (int nt = 0; nt < 4; nt++)
            #pragma unroll
            for (int r = 0; r < 4; r++) acc[mt][nt][r] = 0.f;

    load_tile(0, 0);
    CP_COMMIT();

    for (int kt = 0; kt < ktiles; kt++) {
        const int cur = kt & 1;
        if (kt + 1 < ktiles) {
            load_tile(cur ^ 1, kt + 1);
            CP_COMMIT();
            CP_WAIT(1);
        } else {
            CP_WAIT(0);
        }
        __syncthreads();

        const float* as = As[cur];
        const float* bs = Bs[cur];

        #pragma unroll
        for (int ks = 0; ks < 4; ks++) {
            const int k8 = ks << 3;
            uint32_t af[4][4];
            #pragma unroll
            for (int mt = 0; mt < 4; mt++) {
                int r0 = warp_m * 64 + mt * 16 + gid;
                af[mt][0] = f2tf32(as[(r0    ) * AS_STRIDE + k8 + tg    ]);
                af[mt][1] = f2tf32(as[(r0 + 8) * AS_STRIDE + k8 + tg    ]);
                af[mt][2] = f2tf32(as[(r0    ) * AS_STRIDE + k8 + tg + 4]);
                af[mt][3] = f2tf32(as[(r0 + 8) * AS_STRIDE + k8 + tg + 4]);
            }
            uint32_t bf[4][2];
            #pragma unroll
            for (int nt = 0; nt < 4; nt++) {
                int c = warp_n * 32 + nt * 8 + gid;
                bf[nt][0] = f2tf32(bs[(k8 + tg    ) * BS_STRIDE + c]);
                bf[nt][1] = f2tf32(bs[(k8 + tg + 4) * BS_STRIDE + c]);
            }
            #pragma unroll
            for (int mt = 0; mt < 4; mt++)
                #pragma unroll
                for (int nt = 0; nt < 4; nt++)
                    mma_tf32(acc[mt][nt], af[mt], bf[nt]);
        }
        __syncthreads();
    }

    // Epilogue: add bias, write fp32
    #pragma unroll
    for (int mt = 0; mt < 4; mt++) {
        #pragma unroll
        for (int nt = 0; nt < 4; nt++) {
            int r = bm + warp_m * 64 + mt * 16 + gid;
            int c = bn + warp_n * 32 + nt * 8 + (tg << 1);
            float b0 = bias[c], b1 = bias[c + 1];
            float2 v0 = make_float2(acc[mt][nt][0] + b0, acc[mt][nt][1] + b1);
            float2 v1 = make_float2(acc[mt][nt][2] + b0, acc[mt][nt][3] + b1);
            *(float2*)(C + (size_t)r * N + c)       = v0;
            *(float2*)(C + (size_t)(r + 8) * N + c) = v1;
        }
    }
}

// ---------------------------------------------------------------------------
// Flash attention (causal, online softmax), fp32.
// ---------------------------------------------------------------------------
__global__ __launch_bounds__(128) void flash_kernel(
    const float* __restrict__ qkv, float* __restrict__ y)
{
    extern __shared__ float sm[];
    float (*Qs)[65] = (float(*)[65])sm;
    float (*KP)[65] = (float(*)[65])(sm + 64 * 65);
    float (*Vs)[65] = (float(*)[65])(sm + 2 * 64 * 65);

    const int qb = blockIdx.x, h = blockIdx.y, b = blockIdx.z;
    const int tid = threadIdx.x;
    const int tx = tid & 7;
    const int ty = tid >> 3;

    const size_t rs = (size_t)3 * Cc;
    const float* qbase = qkv + ((size_t)(b * Tt) + (size_t)qb * 64) * rs + h * Dd;

    #pragma unroll
    for (int it = 0; it < 8; it++) {
        int idx = tid + 128 * it;
        int r = idx >> 4, c = (idx & 15) << 2;
        float4 v = *(const float4*)(qbase + (size_t)r * rs + c);
        Qs[r][c + 0] = v.x; Qs[r][c + 1] = v.y;
        Qs[r][c + 2] = v.z; Qs[r][c + 3] = v.w;
    }

    float o[4][8];
    float mrow[4], lrow[4];
    #pragma unroll
    for (int i = 0; i < 4; i++) {
        mrow[i] = -INFINITY; lrow[i] = 0.f;
        #pragma unroll
        for (int j = 0; j < 8; j++) o[i][j] = 0.f;
    }

    const float scale = 0.125f;

    for (int kb = 0; kb <= qb; kb++) {
        __syncthreads();

        const float* kbase = qkv + ((size_t)(b * Tt) + (size_t)kb * 64) * rs + Cc + h * Dd;
        const float* vbase = kbase + Cc;
        #pragma unroll
        for (int it = 0; it < 8; it++) {
            int idx = tid + 128 * it;
            int r = idx >> 4, c = (idx & 15) << 2;
            float4 kv = *(const float4*)(kbase + (size_t)r * rs + c);
            KP[r][c + 0] = kv.x; KP[r][c + 1] = kv.y;
            KP[r][c + 2] = kv.z; KP[r][c + 3] = kv.w;
            float4 vv = *(const float4*)(vbase + (size_t)r * rs + c);
            Vs[r][c + 0] = vv.x; Vs[r][c + 1] = vv.y;
            Vs[r][c + 2] = vv.z; Vs[r][c + 3] = vv.w;
        }
        __syncthreads();

        float s[4][8];
        #pragma unroll
        for (int i = 0; i < 4; i++)
            #pragma unroll
            for (int j = 0; j < 8; j++) s[i][j] = 0.f;

        #pragma unroll 8
        for (int d = 0; d < 64; d++) {
            float qv[4], kv[8];
            #pragma unroll
            for (int i = 0; i < 4; i++) qv[i] = Qs[(ty << 2) + i][d];
            #pragma unroll
            for (int j = 0; j < 8; j++) kv[j] = KP[(tx << 3) + j][d];
            #pragma unroll
            for (int i = 0; i < 4; i++)
                #pragma unroll
                for (int j = 0; j < 8; j++) s[i][j] += qv[i] * kv[j];
        }

        if (kb == qb) {
            #pragma unroll
            for (int i = 0; i < 4; i++) {
                int qg = (ty << 2) + i;
                #pragma unroll
                for (int j = 0; j < 8; j++) {
                    int kg = (tx << 3) + j;
                    s[i][j] = (kg <= qg) ? s[i][j] * scale : -INFINITY;
                }
            }
        } else {
            #pragma unroll
            for (int i = 0; i < 4; i++)
                #pragma unroll
                for (int j = 0; j < 8; j++) s[i][j] *= scale;
        }

        #pragma unroll
        for (int i = 0; i < 4; i++) {
            float mx = s[i][0];
            #pragma unroll
            for (int j = 1; j < 8; j++) mx = fmaxf(mx, s[i][j]);
            mx = fmaxf(mx, __shfl_xor_sync(0xffffffffu, mx, 1));
            mx = fmaxf(mx, __shfl_xor_sync(0xffffffffu, mx, 2));
            mx = fmaxf(mx, __shfl_xor_sync(0xffffffffu, mx, 4));
            float mn = fmaxf(mrow[i], mx);
            float alpha = __expf(mrow[i] - mn);
            mrow[i] = mn;
            float rsum = 0.f;
            #pragma unroll
            for (int j = 0; j < 8; j++) {
                s[i][j] = __expf(s[i][j] - mn);
                rsum += s[i][j];
            }
            rsum += __shfl_xor_sync(0xffffffffu, rsum, 1);
            rsum += __shfl_xor_sync(0xffffffffu, rsum, 2);
            rsum += __shfl_xor_sync(0xffffffffu, rsum, 4);
            lrow[i] = lrow[i] * alpha + rsum;
            #pragma unroll
            for (int j = 0; j < 8; j++) o[i][j] *= alpha;
        }

        __syncthreads();
        #pragma unroll
        for (int i = 0; i < 4; i++)
            #pragma unroll
            for (int j = 0; j < 8; j++)
                KP[(ty << 2) + i][(tx << 3) + j] = s[i][j];
        __syncthreads();

        #pragma unroll 8
        for (int c = 0; c < 64; c++) {
            float pv[4], vv[8];
            #pragma unroll
            for (int i = 0; i < 4; i++) pv[i] = KP[(ty << 2) + i][c];
            #pragma unroll
            for (int j = 0; j < 8; j++) vv[j] = Vs[c][(tx << 3) + j];
            #pragma unroll
            for (int i = 0; i < 4; i++)
                #pragma unroll
                for (int j = 0; j < 8; j++) o[i][j] += pv[i] * vv[j];
        }
    }

    #pragma unroll
    for (int i = 0; i < 4; i++) {
        float inv = 1.f / lrow[i];
        int r = qb * 64 + (ty << 2) + i;
        float* yrow = y + ((size_t)(b * Tt) + r) * Cc + h * Dd + (tx << 3);
        #pragma unroll
        for (int j = 0; j < 8; j++) yrow[j] = o[i][j] * inv;
    }
}

// ---------------------------------------------------------------------------
extern "C" void kernel_launch(void* const* d_in, const int* in_sizes, int n_in,
                              void* d_out, int out_size)
{
    const float* x  = (const float*)d_in[0];
    const float* Wa = (const float*)d_in[1];
    const float* ba = (const float*)d_in[2];
    const float* Wp = (const float*)d_in[3];
    const float* bp = (const float*)d_in[4];
    float* out = (float*)d_out;

    float *qkv, *y;
    cudaGetSymbolAddress((void**)&qkv, g_qkv);
    cudaGetSymbolAddress((void**)&y,   g_y);

    const int M = Bb * Tt;           // 8192
    const int N1 = 3 * Cc;           // 3072

    const int gemm_smem = (2 * A_TILE_FLOATS + 2 * B_TILE_FLOATS) * (int)sizeof(float); // 71680
    static int attr_set = 0;
    if (!attr_set) {
        cudaFuncSetAttribute(tf32_gemm_bias_kernel, cudaFuncAttributeMaxDynamicSharedMemorySize, gemm_smem);
        cudaFuncSetAttribute(flash_kernel, cudaFuncAttributeMaxDynamicSharedMemorySize, 3 * 64 * 65 * (int)sizeof(float));
        attr_set = 1;
    }

    // GEMM1: qkv = x @ W_attn + b_attn
    tf32_gemm_bias_kernel<<<dim3(N1 / 128, M / 128), 256, gemm_smem>>>(x, Wa, ba, qkv, M, N1, Cc);

    // Flash attention
    const int smem_bytes = 3 * 64 * 65 * (int)sizeof(float);
    flash_kernel<<<dim3(Tt / 64, Hh, Bb), 128, smem_bytes>>>(qkv, y);

    // GEMM2: out = y @ W_proj + b_proj
    tf32_gemm_bias_kernel<<<dim3(Cc / 128, M / 128), 256, gemm_smem>>>(y, Wp, bp, out, M, Cc, Cc);
}

// round 5
// speedup vs baseline: 3.0975x; 1.9596x over previous
#include <cuda_runtime.h>
#include <cstdint>
#include <math.h>

#define Bb 4
#define Tt 2048
#define Cc 1024
#define Hh 16
#define Dd 64

// Scratch (allocation-free rule: device globals)
__device__ float g_qkv[(size_t)Bb * Tt * 3 * Cc];  // 25.2M floats
__device__ float g_y[(size_t)Bb * Tt * Cc];        // 8.4M floats

// ---------------------------------------------------------------------------
// Helpers
// ---------------------------------------------------------------------------
__device__ __forceinline__ uint32_t f2tf32(float f) {
    uint32_t r;
    asm("cvt.rna.tf32.f32 %0, %1;" : "=r"(r) : "f"(f));
    return r;
}

__device__ __forceinline__ void mma_tf32(float c[4], const uint32_t a[4], const uint32_t b[2]) {
    asm volatile(
        "mma.sync.aligned.m16n8k8.row.col.f32.tf32.tf32.f32 "
        "{%0,%1,%2,%3}, {%4,%5,%6,%7}, {%8,%9}, {%0,%1,%2,%3};\n"
        : "+f"(c[0]), "+f"(c[1]), "+f"(c[2]), "+f"(c[3])
        : "r"(a[0]), "r"(a[1]), "r"(a[2]), "r"(a[3]), "r"(b[0]), "r"(b[1]));
}

__device__ __forceinline__ void cp_async16(void* smem_dst, const void* gmem_src) {
    uint32_t s = (uint32_t)__cvta_generic_to_shared(smem_dst);
    asm volatile("cp.async.cg.shared.global [%0], [%1], 16;\n" :: "r"(s), "l"(gmem_src));
}
#define CP_COMMIT() asm volatile("cp.async.commit_group;\n" ::: "memory")
#define CP_WAIT(n)  asm volatile("cp.async.wait_group %0;\n" :: "n"(n) : "memory")

// ---------------------------------------------------------------------------
// TF32 tensor-core GEMM + bias (unchanged from R2/R4 passing version)
// ---------------------------------------------------------------------------
#define AS_STRIDE 36
#define BS_STRIDE 136
#define A_TILE_FLOATS (128 * AS_STRIDE)  // 4608
#define B_TILE_FLOATS (32 * BS_STRIDE)   // 4352

__global__ __launch_bounds__(256) void tf32_gemm_bias_kernel(
    const float* __restrict__ A, const float* __restrict__ B,
    const float* __restrict__ bias, float* __restrict__ C,
    int M, int N, int K)
{
    extern __shared__ float sm[];
    float* As[2] = { sm, sm + A_TILE_FLOATS };
    float* Bs[2] = { sm + 2 * A_TILE_FLOATS, sm + 2 * A_TILE_FLOATS + B_TILE_FLOATS };

    const int tid  = threadIdx.x;
    const int lane = tid & 31, wid = tid >> 5;
    const int warp_m = wid >> 2;
    const int warp_n = wid & 3;
    const int gid = lane >> 2;
    const int tg  = lane & 3;

    const int bm = blockIdx.y * 128;
    const int bn = blockIdx.x * 128;

    const int a_row = tid >> 3;
    const int a_col = (tid & 7) << 2;
    const int b_r0 = tid >> 5;
    const int b_c0 = (tid & 31) << 2;

    const int ktiles = K >> 5;

    auto load_tile = [&](int buf, int kt) {
        const float* Ag = A + (size_t)(bm) * K + kt * 32;
        #pragma unroll
        for (int p = 0; p < 4; p++) {
            int r = a_row + 32 * p;
            cp_async16(&As[buf][r * AS_STRIDE + a_col], Ag + (size_t)r * K + a_col);
        }
        const float* Bg = B + (size_t)(kt * 32) * N + bn;
        #pragma unroll
        for (int p = 0; p < 4; p++) {
            int r = b_r0 + 8 * p;
            cp_async16(&Bs[buf][r * BS_STRIDE + b_c0], Bg + (size_t)r * N + b_c0);
        }
    };

    float acc[4][4][4];
    #pragma unroll
    for (int mt = 0; mt < 4; mt++)
        #pragma unroll
        for (int nt = 0; nt < 4; nt++)
            #pragma unroll
            for (int r = 0; r < 4; r++) acc[mt][nt][r] = 0.f;

    load_tile(0, 0);
    CP_COMMIT();

    for (int kt = 0; kt < ktiles; kt++) {
        const int cur = kt & 1;
        if (kt + 1 < ktiles) {
            load_tile(cur ^ 1, kt + 1);
            CP_COMMIT();
            CP_WAIT(1);
        } else {
            CP_WAIT(0);
        }
        __syncthreads();

        const float* as = As[cur];
        const float* bs = Bs[cur];

        #pragma unroll
        for (int ks = 0; ks < 4; ks++) {
            const int k8 = ks << 3;
            uint32_t af[4][4];
            #pragma unroll
            for (int mt = 0; mt < 4; mt++) {
                int r0 = warp_m * 64 + mt * 16 + gid;
                af[mt][0] = f2tf32(as[(r0    ) * AS_STRIDE + k8 + tg    ]);
                af[mt][1] = f2tf32(as[(r0 + 8) * AS_STRIDE + k8 + tg    ]);
                af[mt][2] = f2tf32(as[(r0    ) * AS_STRIDE + k8 + tg + 4]);
                af[mt][3] = f2tf32(as[(r0 + 8) * AS_STRIDE + k8 + tg + 4]);
            }
            uint32_t bf[4][2];
            #pragma unroll
            for (int nt = 0; nt < 4; nt++) {
                int c = warp_n * 32 + nt * 8 + gid;
                bf[nt][0] = f2tf32(bs[(k8 + tg    ) * BS_STRIDE + c]);
                bf[nt][1] = f2tf32(bs[(k8 + tg + 4) * BS_STRIDE + c]);
            }
            #pragma unroll
            for (int mt = 0; mt < 4; mt++)
                #pragma unroll
                for (int nt = 0; nt < 4; nt++)
                    mma_tf32(acc[mt][nt], af[mt], bf[nt]);
        }
        __syncthreads();
    }

    #pragma unroll
    for (int mt = 0; mt < 4; mt++) {
        #pragma unroll
        for (int nt = 0; nt < 4; nt++) {
            int r = bm + warp_m * 64 + mt * 16 + gid;
            int c = bn + warp_n * 32 + nt * 8 + (tg << 1);
            float b0 = bias[c], b1 = bias[c + 1];
            float2 v0 = make_float2(acc[mt][nt][0] + b0, acc[mt][nt][1] + b1);
            float2 v1 = make_float2(acc[mt][nt][2] + b0, acc[mt][nt][3] + b1);
            *(float2*)(C + (size_t)r * N + c)       = v0;
            *(float2*)(C + (size_t)(r + 8) * N + c) = v1;
        }
    }
}

// ---------------------------------------------------------------------------
// Tensor-core flash attention (causal, online softmax), tf32 MMA.
// Block 128 threads = 4 warps; each warp owns 16 Q rows of the 64-row tile.
// Smem: Qs [64][68], KPs [64][68] (K tile, reused for P), Vs [64][72].
// Strides: 68 % 32 == 4 -> bank 4*gid+tg (bijective); 72 % 32 == 8 -> 8*tg+gid.
// ---------------------------------------------------------------------------
#define QS_ST 68
#define VS_ST 72
#define FL_SMEM_FLOATS (64 * QS_ST * 2 + 64 * VS_ST)  // 13312

__global__ __launch_bounds__(128) void flash_tc_kernel(
    const float* __restrict__ qkv, float* __restrict__ y)
{
    extern __shared__ float sm[];
    float* Qs  = sm;                       // [64][68]
    float* KPs = sm + 64 * QS_ST;          // [64][68]
    float* Vs  = sm + 2 * 64 * QS_ST;      // [64][72]

    const int qb = blockIdx.x, h = blockIdx.y, b = blockIdx.z;
    const int tid = threadIdx.x;
    const int lane = tid & 31, w = tid >> 5;
    const int gid = lane >> 2, tg = lane & 3;

    const size_t rs = (size_t)3 * Cc;
    const float* qbase = qkv + ((size_t)(b * Tt) + (size_t)qb * 64) * rs + h * Dd;

    // Load Q tile via cp.async
    #pragma unroll
    for (int it = 0; it < 8; it++) {
        int idx = tid + 128 * it;
        int r = idx >> 4, c = (idx & 15) << 2;
        cp_async16(&Qs[r * QS_ST + c], qbase + (size_t)r * rs + c);
    }
    CP_COMMIT();
    CP_WAIT(0);
    __syncthreads();

    // Q A-fragments: loaded once, reused over all KV tiles.
    uint32_t qa[8][4];
    {
        const int r0 = w * 16 + gid;
        #pragma unroll
        for (int kk = 0; kk < 8; kk++) {
            const int k8 = kk << 3;
            qa[kk][0] = f2tf32(Qs[(r0    ) * QS_ST + k8 + tg    ]);
            qa[kk][1] = f2tf32(Qs[(r0 + 8) * QS_ST + k8 + tg    ]);
            qa[kk][2] = f2tf32(Qs[(r0    ) * QS_ST + k8 + tg + 4]);
            qa[kk][3] = f2tf32(Qs[(r0 + 8) * QS_ST + k8 + tg + 4]);
        }
    }

    float o[8][4];
    #pragma unroll
    for (int nt = 0; nt < 8; nt++)
        #pragma unroll
        for (int r = 0; r < 4; r++) o[nt][r] = 0.f;
    float m0 = -INFINITY, m1 = -INFINITY, l0 = 0.f, l1 = 0.f;

    const float scale = 0.125f;  // 1/sqrt(64)

    for (int kb = 0; kb <= qb; kb++) {
        __syncthreads();  // prior P/V consumers done before overwriting smem

        const float* kbase = qkv + ((size_t)(b * Tt) + (size_t)kb * 64) * rs + Cc + h * Dd;
        const float* vbase = kbase + Cc;
        #pragma unroll
        for (int it = 0; it < 8; it++) {
            int idx = tid + 128 * it;
            int r = idx >> 4, c = (idx & 15) << 2;
            cp_async16(&KPs[r * QS_ST + c], kbase + (size_t)r * rs + c);
            cp_async16(&Vs [r * VS_ST + c], vbase + (size_t)r * rs + c);
        }
        CP_COMMIT();
        CP_WAIT(0);
        __syncthreads();

        // ---- S = Q K^T ----
        float s[8][4];
        #pragma unroll
        for (int nt = 0; nt < 8; nt++) {
            #pragma unroll
            for (int r = 0; r < 4; r++) s[nt][r] = 0.f;
            const int n = nt * 8 + gid;
            #pragma unroll
            for (int kk = 0; kk < 8; kk++) {
                const int k8 = kk << 3;
                uint32_t bf[2];
                bf[0] = f2tf32(KPs[n * QS_ST + k8 + tg    ]);
                bf[1] = f2tf32(KPs[n * QS_ST + k8 + tg + 4]);
                mma_tf32(s[nt], qa[kk], bf);
            }
        }

        // ---- scale + causal mask ----
        if (kb == qb) {
            const int ql0 = w * 16 + gid, ql1 = ql0 + 8;
            #pragma unroll
            for (int nt = 0; nt < 8; nt++) {
                const int kl = nt * 8 + (tg << 1);
                s[nt][0] = (kl     <= ql0) ? s[nt][0] * scale : -INFINITY;
                s[nt][1] = (kl + 1 <= ql0) ? s[nt][1] * scale : -INFINITY;
                s[nt][2] = (kl     <= ql1) ? s[nt][2] * scale : -INFINITY;
                s[nt][3] = (kl + 1 <= ql1) ? s[nt][3] * scale : -INFINITY;
            }
        } else {
            #pragma unroll
            for (int nt = 0; nt < 8; nt++)
                #pragma unroll
                for (int r = 0; r < 4; r++) s[nt][r] *= scale;
        }

        // ---- online softmax (rows gid / gid+8; reduce across tg lanes) ----
        float mx0 = -INFINITY, mx1 = -INFINITY;
        #pragma unroll
        for (int nt = 0; nt < 8; nt++) {
            mx0 = fmaxf(mx0, fmaxf(s[nt][0], s[nt][1]));
            mx1 = fmaxf(mx1, fmaxf(s[nt][2], s[nt][3]));
        }
        mx0 = fmaxf(mx0, __shfl_xor_sync(0xffffffffu, mx0, 1));
        mx0 = fmaxf(mx0, __shfl_xor_sync(0xffffffffu, mx0, 2));
        mx1 = fmaxf(mx1, __shfl_xor_sync(0xffffffffu, mx1, 1));
        mx1 = fmaxf(mx1, __shfl_xor_sync(0xffffffffu, mx1, 2));

        const float nm0 = fmaxf(m0, mx0);
        const float nm1 = fmaxf(m1, mx1);
        const float a0 = __expf(m0 - nm0);
        const float a1 = __expf(m1 - nm1);
        m0 = nm0; m1 = nm1;

        float sum0 = 0.f, sum1 = 0.f;
        #pragma unroll
        for (int nt = 0; nt < 8; nt++) {
            s[nt][0] = __expf(s[nt][0] - nm0);
            s[nt][1] = __expf(s[nt][1] - nm0);
            s[nt][2] = __expf(s[nt][2] - nm1);
            s[nt][3] = __expf(s[nt][3] - nm1);
            sum0 += s[nt][0] + s[nt][1];
            sum1 += s[nt][2] + s[nt][3];
        }
        sum0 += __shfl_xor_sync(0xffffffffu, sum0, 1);
        sum0 += __shfl_xor_sync(0xffffffffu, sum0, 2);
        sum1 += __shfl_xor_sync(0xffffffffu, sum1, 1);
        sum1 += __shfl_xor_sync(0xffffffffu, sum1, 2);
        l0 = l0 * a0 + sum0;
        l1 = l1 * a1 + sum1;

        #pragma unroll
        for (int nt = 0; nt < 8; nt++) {
            o[nt][0] *= a0; o[nt][1] *= a0;
            o[nt][2] *= a1; o[nt][3] *= a1;
        }

        // ---- P -> smem (reuse K buffer) ----
        __syncthreads();  // all warps done reading K
        {
            const int r0 = w * 16 + gid;
            #pragma unroll
            for (int nt = 0; nt < 8; nt++) {
                const int c = nt * 8 + (tg << 1);
                *(float2*)&KPs[(r0    ) * QS_ST + c] = make_float2(s[nt][0], s[nt][1]);
                *(float2*)&KPs[(r0 + 8) * QS_ST + c] = make_float2(s[nt][2], s[nt][3]);
            }
        }
        __syncthreads();

        // ---- O += P @ V ----
        uint32_t pa[8][4];
        {
            const int r0 = w * 16 + gid;
            #pragma unroll
            for (int kk = 0; kk < 8; kk++) {
                const int k8 = kk << 3;
                pa[kk][0] = f2tf32(KPs[(r0    ) * QS_ST + k8 + tg    ]);
                pa[kk][1] = f2tf32(KPs[(r0 + 8) * QS_ST + k8 + tg    ]);
                pa[kk][2] = f2tf32(KPs[(r0    ) * QS_ST + k8 + tg + 4]);
                pa[kk][3] = f2tf32(KPs[(r0 + 8) * QS_ST + k8 + tg + 4]);
            }
        }
        #pragma unroll
        for (int nt = 0; nt < 8; nt++) {
            const int n = nt * 8 + gid;
            #pragma unroll
            for (int kk = 0; kk < 8; kk++) {
                const int k8 = kk << 3;
                uint32_t bf[2];
                bf[0] = f2tf32(Vs[(k8 + tg    ) * VS_ST + n]);
                bf[1] = f2tf32(Vs[(k8 + tg + 4) * VS_ST + n]);
                mma_tf32(o[nt], pa[kk], bf);
            }
        }
    }

    // ---- normalize + write ----
    const float inv0 = 1.f / l0;
    const float inv1 = 1.f / l1;
    const int r0g = qb * 64 + w * 16 + gid;
    float* y0 = y + ((size_t)(b * Tt) + r0g) * Cc + h * Dd;
    float* y1 = y0 + 8 * Cc;
    #pragma unroll
    for (int nt = 0; nt < 8; nt++) {
        const int c = nt * 8 + (tg << 1);
        *(float2*)(y0 + c) = make_float2(o[nt][0] * inv0, o[nt][1] * inv0);
        *(float2*)(y1 + c) = make_float2(o[nt][2] * inv1, o[nt][3] * inv1);
    }
}

// ---------------------------------------------------------------------------
extern "C" void kernel_launch(void* const* d_in, const int* in_sizes, int n_in,
                              void* d_out, int out_size)
{
    const float* x  = (const float*)d_in[0];
    const float* Wa = (const float*)d_in[1];
    const float* ba = (const float*)d_in[2];
    const float* Wp = (const float*)d_in[3];
    const float* bp = (const float*)d_in[4];
    float* out = (float*)d_out;

    float *qkv, *y;
    cudaGetSymbolAddress((void**)&qkv, g_qkv);
    cudaGetSymbolAddress((void**)&y,   g_y);

    const int M = Bb * Tt;           // 8192
    const int N1 = 3 * Cc;           // 3072

    const int gemm_smem  = (2 * A_TILE_FLOATS + 2 * B_TILE_FLOATS) * (int)sizeof(float); // 71680
    const int flash_smem = FL_SMEM_FLOATS * (int)sizeof(float);                          // 53248
    cudaFuncSetAttribute(tf32_gemm_bias_kernel, cudaFuncAttributeMaxDynamicSharedMemorySize, gemm_smem);
    cudaFuncSetAttribute(flash_tc_kernel, cudaFuncAttributeMaxDynamicSharedMemorySize, flash_smem);

    // GEMM1: qkv = x @ W_attn + b_attn
    tf32_gemm_bias_kernel<<<dim3(N1 / 128, M / 128), 256, gemm_smem>>>(x, Wa, ba, qkv, M, N1, Cc);

    // Flash attention (tensor-core)
    flash_tc_kernel<<<dim3(Tt / 64, Hh, Bb), 128, flash_smem>>>(qkv, y);

    // GEMM2: out = y @ W_proj + b_proj
    tf32_gemm_bias_kernel<<<dim3(Cc / 128, M / 128), 256, gemm_smem>>>(y, Wp, bp, out, M, Cc, Cc);
}

// round 6
// speedup vs baseline: 3.9130x; 1.2633x over previous
#include <cuda_runtime.h>
#include <cstdint>
#include <math.h>

#define Bb 4
#define Tt 2048
#define Cc 1024
#define Hh 16
#define Dd 64

// Scratch (allocation-free rule: device globals)
__device__ float g_qkv[(size_t)Bb * Tt * 3 * Cc];   // qkv (written tf32-rounded)
__device__ float g_y[(size_t)Bb * Tt * Cc];         // y   (written tf32-rounded)
__device__ float g_xr[(size_t)Bb * Tt * Cc];        // x  pre-rounded
__device__ float g_war[(size_t)Cc * 3 * Cc];        // W_attn pre-rounded
__device__ float g_wpr[(size_t)Cc * Cc];            // W_proj pre-rounded

// ---------------------------------------------------------------------------
// Helpers
// ---------------------------------------------------------------------------
__device__ __forceinline__ uint32_t f2tf32(float f) {
    uint32_t r;
    asm("cvt.rna.tf32.f32 %0, %1;" : "=r"(r) : "f"(f));
    return r;
}
__device__ __forceinline__ float roundtf(float f) { return __uint_as_float(f2tf32(f)); }

__device__ __forceinline__ void mma_tf32(float c[4], const uint32_t a[4], const uint32_t b[2]) {
    asm volatile(
        "mma.sync.aligned.m16n8k8.row.col.f32.tf32.tf32.f32 "
        "{%0,%1,%2,%3}, {%4,%5,%6,%7}, {%8,%9}, {%0,%1,%2,%3};\n"
        : "+f"(c[0]), "+f"(c[1]), "+f"(c[2]), "+f"(c[3])
        : "r"(a[0]), "r"(a[1]), "r"(a[2]), "r"(a[3]), "r"(b[0]), "r"(b[1]));
}

__device__ __forceinline__ void cp_async16(void* smem_dst, const void* gmem_src) {
    uint32_t s = (uint32_t)__cvta_generic_to_shared(smem_dst);
    asm volatile("cp.async.cg.shared.global [%0], [%1], 16;\n" :: "r"(s), "l"(gmem_src));
}
#define CP_COMMIT() asm volatile("cp.async.commit_group;\n" ::: "memory")
#define CP_WAIT(n)  asm volatile("cp.async.wait_group %0;\n" :: "n"(n) : "memory")

// ---------------------------------------------------------------------------
// Pre-round fp32 -> tf32 bit patterns (elementwise, float4)
// ---------------------------------------------------------------------------
__global__ __launch_bounds__(256) void preround_kernel(
    const float4* __restrict__ in, float4* __restrict__ out, int n4)
{
    int i = blockIdx.x * blockDim.x + threadIdx.x;
    if (i < n4) {
        float4 v = in[i];
        v.x = roundtf(v.x); v.y = roundtf(v.y);
        v.z = roundtf(v.z); v.w = roundtf(v.w);
        out[i] = v;
    }
}

// ---------------------------------------------------------------------------
// TF32 tensor-core GEMM + bias. Inputs are PRE-ROUNDED tf32 bit patterns.
// BM=BN=128, BK=32, 256 threads, 2 CTAs/SM. ROUND_OUT: round C to tf32.
// ---------------------------------------------------------------------------
#define AS_STRIDE 36
#define BS_STRIDE 136
#define A_TILE_FLOATS (128 * AS_STRIDE)  // 4608
#define B_TILE_FLOATS (32 * BS_STRIDE)   // 4352

template <bool ROUND_OUT>
__global__ __launch_bounds__(256, 2) void tf32_gemm_bias_kernel(
    const float* __restrict__ A, const float* __restrict__ B,
    const float* __restrict__ bias, float* __restrict__ C,
    int M, int N, int K)
{
    extern __shared__ float sm[];
    float* As[2] = { sm, sm + A_TILE_FLOATS };
    float* Bs[2] = { sm + 2 * A_TILE_FLOATS, sm + 2 * A_TILE_FLOATS + B_TILE_FLOATS };

    const int tid  = threadIdx.x;
    const int lane = tid & 31, wid = tid >> 5;
    const int warp_m = wid >> 2;
    const int warp_n = wid & 3;
    const int gid = lane >> 2;
    const int tg  = lane & 3;

    const int bm = blockIdx.y * 128;
    const int bn = blockIdx.x * 128;

    const int a_row = tid >> 3;
    const int a_col = (tid & 7) << 2;
    const int b_r0 = tid >> 5;
    const int b_c0 = (tid & 31) << 2;

    const int ktiles = K >> 5;

    auto load_tile = [&](int buf, int kt) {
        const float* Ag = A + (size_t)(bm) * K + kt * 32;
        #pragma unroll
        for (int p = 0; p < 4; p++) {
            int r = a_row + 32 * p;
            cp_async16(&As[buf][r * AS_STRIDE + a_col], Ag + (size_t)r * K + a_col);
        }
        const float* Bg = B + (size_t)(kt * 32) * N + bn;
        #pragma unroll
        for (int p = 0; p < 4; p++) {
            int r = b_r0 + 8 * p;
            cp_async16(&Bs[buf][r * BS_STRIDE + b_c0], Bg + (size_t)r * N + b_c0);
        }
    };

    float acc[4][4][4];
    #pragma unroll
    for (int mt = 0; mt < 4; mt++)
        #pragma unroll
        for (int nt = 0; nt < 4; nt++)
            #pragma unroll
            for (int r = 0; r < 4; r++) acc[mt][nt][r] = 0.f;

    load_tile(0, 0);
    CP_COMMIT();

    for (int kt = 0; kt < ktiles; kt++) {
        const int cur = kt & 1;
        if (kt + 1 < ktiles) {
            load_tile(cur ^ 1, kt + 1);
            CP_COMMIT();
            CP_WAIT(1);
        } else {
            CP_WAIT(0);
        }
        __syncthreads();

        const float* as = As[cur];
        const float* bs = Bs[cur];

        #pragma unroll
        for (int ks = 0; ks < 4; ks++) {
            const int k8 = ks << 3;
            uint32_t af[4][4];
            #pragma unroll
            for (int mt = 0; mt < 4; mt++) {
                int r0 = warp_m * 64 + mt * 16 + gid;
                af[mt][0] = __float_as_uint(as[(r0    ) * AS_STRIDE + k8 + tg    ]);
                af[mt][1] = __float_as_uint(as[(r0 + 8) * AS_STRIDE + k8 + tg    ]);
                af[mt][2] = __float_as_uint(as[(r0    ) * AS_STRIDE + k8 + tg + 4]);
                af[mt][3] = __float_as_uint(as[(r0 + 8) * AS_STRIDE + k8 + tg + 4]);
            }
            uint32_t bf[4][2];
            #pragma unroll
            for (int nt = 0; nt < 4; nt++) {
                int c = warp_n * 32 + nt * 8 + gid;
                bf[nt][0] = __float_as_uint(bs[(k8 + tg    ) * BS_STRIDE + c]);
                bf[nt][1] = __float_as_uint(bs[(k8 + tg + 4) * BS_STRIDE + c]);
            }
            #pragma unroll
            for (int mt = 0; mt < 4; mt++)
                #pragma unroll
                for (int nt = 0; nt < 4; nt++)
                    mma_tf32(acc[mt][nt], af[mt], bf[nt]);
        }
        __syncthreads();
    }

    #pragma unroll
    for (int mt = 0; mt < 4; mt++) {
        #pragma unroll
        for (int nt = 0; nt < 4; nt++) {
            int r = bm + warp_m * 64 + mt * 16 + gid;
            int c = bn + warp_n * 32 + nt * 8 + (tg << 1);
            float b0 = bias[c], b1 = bias[c + 1];
            float2 v0, v1;
            if (ROUND_OUT) {
                v0 = make_float2(roundtf(acc[mt][nt][0] + b0), roundtf(acc[mt][nt][1] + b1));
                v1 = make_float2(roundtf(acc[mt][nt][2] + b0), roundtf(acc[mt][nt][3] + b1));
            } else {
                v0 = make_float2(acc[mt][nt][0] + b0, acc[mt][nt][1] + b1);
                v1 = make_float2(acc[mt][nt][2] + b0, acc[mt][nt][3] + b1);
            }
            *(float2*)(C + (size_t)r * N + c)       = v0;
            *(float2*)(C + (size_t)(r + 8) * N + c) = v1;
        }
    }
}

// ---------------------------------------------------------------------------
// Tensor-core flash attention. qkv is pre-rounded tf32 bit patterns.
// Block 128 threads = 4 warps; each warp owns 16 Q rows of the 64-row tile.
// ---------------------------------------------------------------------------
#define QS_ST 68
#define VS_ST 72
#define FL_SMEM_FLOATS (64 * QS_ST * 2 + 64 * VS_ST)  // 13312

__global__ __launch_bounds__(128) void flash_tc_kernel(
    const float* __restrict__ qkv, float* __restrict__ y)
{
    extern __shared__ float sm[];
    float* Qs  = sm;                       // [64][68]
    float* KPs = sm + 64 * QS_ST;          // [64][68]
    float* Vs  = sm + 2 * 64 * QS_ST;      // [64][72]

    const int qb = blockIdx.x, h = blockIdx.y, b = blockIdx.z;
    const int tid = threadIdx.x;
    const int lane = tid & 31, w = tid >> 5;
    const int gid = lane >> 2, tg = lane & 3;

    const size_t rs = (size_t)3 * Cc;
    const float* qbase = qkv + ((size_t)(b * Tt) + (size_t)qb * 64) * rs + h * Dd;

    #pragma unroll
    for (int it = 0; it < 8; it++) {
        int idx = tid + 128 * it;
        int r = idx >> 4, c = (idx & 15) << 2;
        cp_async16(&Qs[r * QS_ST + c], qbase + (size_t)r * rs + c);
    }
    CP_COMMIT();
    CP_WAIT(0);
    __syncthreads();

    uint32_t qa[8][4];
    {
        const int r0 = w * 16 + gid;
        #pragma unroll
        for (int kk = 0; kk < 8; kk++) {
            const int k8 = kk << 3;
            qa[kk][0] = __float_as_uint(Qs[(r0    ) * QS_ST + k8 + tg    ]);
            qa[kk][1] = __float_as_uint(Qs[(r0 + 8) * QS_ST + k8 + tg    ]);
            qa[kk][2] = __float_as_uint(Qs[(r0    ) * QS_ST + k8 + tg + 4]);
            qa[kk][3] = __float_as_uint(Qs[(r0 + 8) * QS_ST + k8 + tg + 4]);
        }
    }

    float o[8][4];
    #pragma unroll
    for (int nt = 0; nt < 8; nt++)
        #pragma unroll
        for (int r = 0; r < 4; r++) o[nt][r] = 0.f;
    float m0 = -INFINITY, m1 = -INFINITY, l0 = 0.f, l1 = 0.f;

    const float scale = 0.125f;

    for (int kb = 0; kb <= qb; kb++) {
        __syncthreads();

        const float* kbase = qkv + ((size_t)(b * Tt) + (size_t)kb * 64) * rs + Cc + h * Dd;
        const float* vbase = kbase + Cc;
        #pragma unroll
        for (int it = 0; it < 8; it++) {
            int idx = tid + 128 * it;
            int r = idx >> 4, c = (idx & 15) << 2;
            cp_async16(&KPs[r * QS_ST + c], kbase + (size_t)r * rs + c);
            cp_async16(&Vs [r * VS_ST + c], vbase + (size_t)r * rs + c);
        }
        CP_COMMIT();
        CP_WAIT(0);
        __syncthreads();

        // ---- S = Q K^T ----
        float s[8][4];
        #pragma unroll
        for (int nt = 0; nt < 8; nt++) {
            #pragma unroll
            for (int r = 0; r < 4; r++) s[nt][r] = 0.f;
            const int n = nt * 8 + gid;
            #pragma unroll
            for (int kk = 0; kk < 8; kk++) {
                const int k8 = kk << 3;
                uint32_t bf[2];
                bf[0] = __float_as_uint(KPs[n * QS_ST + k8 + tg    ]);
                bf[1] = __float_as_uint(KPs[n * QS_ST + k8 + tg + 4]);
                mma_tf32(s[nt], qa[kk], bf);
            }
        }

        // ---- scale + causal mask ----
        if (kb == qb) {
            const int ql0 = w * 16 + gid, ql1 = ql0 + 8;
            #pragma unroll
            for (int nt = 0; nt < 8; nt++) {
                const int kl = nt * 8 + (tg << 1);
                s[nt][0] = (kl     <= ql0) ? s[nt][0] * scale : -INFINITY;
                s[nt][1] = (kl + 1 <= ql0) ? s[nt][1] * scale : -INFINITY;
                s[nt][2] = (kl     <= ql1) ? s[nt][2] * scale : -INFINITY;
                s[nt][3] = (kl + 1 <= ql1) ? s[nt][3] * scale : -INFINITY;
            }
        } else {
            #pragma unroll
            for (int nt = 0; nt < 8; nt++)
                #pragma unroll
                for (int r = 0; r < 4; r++) s[nt][r] *= scale;
        }

        // ---- online softmax ----
        float mx0 = -INFINITY, mx1 = -INFINITY;
        #pragma unroll
        for (int nt = 0; nt < 8; nt++) {
            mx0 = fmaxf(mx0, fmaxf(s[nt][0], s[nt][1]));
            mx1 = fmaxf(mx1, fmaxf(s[nt][2], s[nt][3]));
        }
        mx0 = fmaxf(mx0, __shfl_xor_sync(0xffffffffu, mx0, 1));
        mx0 = fmaxf(mx0, __shfl_xor_sync(0xffffffffu, mx0, 2));
        mx1 = fmaxf(mx1, __shfl_xor_sync(0xffffffffu, mx1, 1));
        mx1 = fmaxf(mx1, __shfl_xor_sync(0xffffffffu, mx1, 2));

        const float nm0 = fmaxf(m0, mx0);
        const float nm1 = fmaxf(m1, mx1);
        const float a0 = __expf(m0 - nm0);
        const float a1 = __expf(m1 - nm1);
        m0 = nm0; m1 = nm1;

        float sum0 = 0.f, sum1 = 0.f;
        #pragma unroll
        for (int nt = 0; nt < 8; nt++) {
            s[nt][0] = __expf(s[nt][0] - nm0);
            s[nt][1] = __expf(s[nt][1] - nm0);
            s[nt][2] = __expf(s[nt][2] - nm1);
            s[nt][3] = __expf(s[nt][3] - nm1);
            sum0 += s[nt][0] + s[nt][1];
            sum1 += s[nt][2] + s[nt][3];
        }
        sum0 += __shfl_xor_sync(0xffffffffu, sum0, 1);
        sum0 += __shfl_xor_sync(0xffffffffu, sum0, 2);
        sum1 += __shfl_xor_sync(0xffffffffu, sum1, 1);
        sum1 += __shfl_xor_sync(0xffffffffu, sum1, 2);
        l0 = l0 * a0 + sum0;
        l1 = l1 * a1 + sum1;

        #pragma unroll
        for (int nt = 0; nt < 8; nt++) {
            o[nt][0] *= a0; o[nt][1] *= a0;
            o[nt][2] *= a1; o[nt][3] *= a1;
        }

        // ---- P -> smem (tf32-rounded at store) ----
        __syncthreads();
        {
            const int r0 = w * 16 + gid;
            #pragma unroll
            for (int nt = 0; nt < 8; nt++) {
                const int c = nt * 8 + (tg << 1);
                *(float2*)&KPs[(r0    ) * QS_ST + c] = make_float2(roundtf(s[nt][0]), roundtf(s[nt][1]));
                *(float2*)&KPs[(r0 + 8) * QS_ST + c] = make_float2(roundtf(s[nt][2]), roundtf(s[nt][3]));
            }
        }
        __syncthreads();

        // ---- O += P @ V ----
        uint32_t pa[8][4];
        {
            const int r0 = w * 16 + gid;
            #pragma unroll
            for (int kk = 0; kk < 8; kk++) {
                const int k8 = kk << 3;
                pa[kk][0] = __float_as_uint(KPs[(r0    ) * QS_ST + k8 + tg    ]);
                pa[kk][1] = __float_as_uint(KPs[(r0 + 8) * QS_ST + k8 + tg    ]);
                pa[kk][2] = __float_as_uint(KPs[(r0    ) * QS_ST + k8 + tg + 4]);
                pa[kk][3] = __float_as_uint(KPs[(r0 + 8) * QS_ST + k8 + tg + 4]);
            }
        }
        #pragma unroll
        for (int nt = 0; nt < 8; nt++) {
            const int n = nt * 8 + gid;
            #pragma unroll
            for (int kk = 0; kk < 8; kk++) {
                const int k8 = kk << 3;
                uint32_t bf[2];
                bf[0] = __float_as_uint(Vs[(k8 + tg    ) * VS_ST + n]);
                bf[1] = __float_as_uint(Vs[(k8 + tg + 4) * VS_ST + n]);
                mma_tf32(o[nt], pa[kk], bf);
            }
        }
    }

    // ---- normalize + write (tf32-rounded: y feeds GEMM2's A operand) ----
    const float inv0 = 1.f / l0;
    const float inv1 = 1.f / l1;
    const int r0g = qb * 64 + w * 16 + gid;
    float* y0 = y + ((size_t)(b * Tt) + r0g) * Cc + h * Dd;
    float* y1 = y0 + 8 * Cc;
    #pragma unroll
    for (int nt = 0; nt < 8; nt++) {
        const int c = nt * 8 + (tg << 1);
        *(float2*)(y0 + c) = make_float2(roundtf(o[nt][0] * inv0), roundtf(o[nt][1] * inv0));
        *(float2*)(y1 + c) = make_float2(roundtf(o[nt][2] * inv1), roundtf(o[nt][3] * inv1));
    }
}

// ---------------------------------------------------------------------------
extern "C" void kernel_launch(void* const* d_in, const int* in_sizes, int n_in,
                              void* d_out, int out_size)
{
    const float* x  = (const float*)d_in[0];
    const float* Wa = (const float*)d_in[1];
    const float* ba = (const float*)d_in[2];
    const float* Wp = (const float*)d_in[3];
    const float* bp = (const float*)d_in[4];
    float* out = (float*)d_out;

    float *qkv, *y, *xr, *war, *wpr;
    cudaGetSymbolAddress((void**)&qkv, g_qkv);
    cudaGetSymbolAddress((void**)&y,   g_y);
    cudaGetSymbolAddress((void**)&xr,  g_xr);
    cudaGetSymbolAddress((void**)&war, g_war);
    cudaGetSymbolAddress((void**)&wpr, g_wpr);

    const int M = Bb * Tt;           // 8192
    const int N1 = 3 * Cc;           // 3072

    const int gemm_smem  = (2 * A_TILE_FLOATS + 2 * B_TILE_FLOATS) * (int)sizeof(float); // 71680
    const int flash_smem = FL_SMEM_FLOATS * (int)sizeof(float);                          // 53248
    cudaFuncSetAttribute(tf32_gemm_bias_kernel<true>,  cudaFuncAttributeMaxDynamicSharedMemorySize, gemm_smem);
    cudaFuncSetAttribute(tf32_gemm_bias_kernel<false>, cudaFuncAttributeMaxDynamicSharedMemorySize, gemm_smem);
    cudaFuncSetAttribute(flash_tc_kernel, cudaFuncAttributeMaxDynamicSharedMemorySize, flash_smem);

    // Pre-round inputs to tf32 bit patterns
    {
        int n4x = (M * Cc) / 4, n4a = (Cc * N1) / 4, n4p = (Cc * Cc) / 4;
        preround_kernel<<<(n4x + 255) / 256, 256>>>((const float4*)x,  (float4*)xr,  n4x);
        preround_kernel<<<(n4a + 255) / 256, 256>>>((const float4*)Wa, (float4*)war, n4a);
        preround_kernel<<<(n4p + 255) / 256, 256>>>((const float4*)Wp, (float4*)wpr, n4p);
    }

    // GEMM1: qkv = x @ W_attn + b_attn (output tf32-rounded)
    tf32_gemm_bias_kernel<true><<<dim3(N1 / 128, M / 128), 256, gemm_smem>>>(xr, war, ba, qkv, M, N1, Cc);

    // Flash attention (tensor-core)
    flash_tc_kernel<<<dim3(Tt / 64, Hh, Bb), 128, flash_smem>>>(qkv, y);

    // GEMM2: out = y @ W_proj + b_proj (final output, NOT rounded)
    tf32_gemm_bias_kernel<false><<<dim3(Cc / 128, M / 128), 256, gemm_smem>>>(y, wpr, bp, out, M, Cc, Cc);
}

// round 7
// speedup vs baseline: 4.0947x; 1.0464x over previous
#include <cuda_runtime.h>
#include <cstdint>
#include <math.h>

#define Bb 4
#define Tt 2048
#define Cc 1024
#define Hh 16
#define Dd 64

// Scratch (allocation-free rule: device globals)
__device__ float g_qkv[(size_t)Bb * Tt * 3 * Cc];   // qkv (written tf32-rounded)
__device__ float g_y[(size_t)Bb * Tt * Cc];         // y   (written tf32-rounded)
__device__ float g_xr[(size_t)Bb * Tt * Cc];        // x  pre-rounded
__device__ float g_war[(size_t)Cc * 3 * Cc];        // W_attn pre-rounded
__device__ float g_wpr[(size_t)Cc * Cc];            // W_proj pre-rounded

// ---------------------------------------------------------------------------
// Helpers
// ---------------------------------------------------------------------------
__device__ __forceinline__ uint32_t f2tf32(float f) {
    uint32_t r;
    asm("cvt.rna.tf32.f32 %0, %1;" : "=r"(r) : "f"(f));
    return r;
}
__device__ __forceinline__ float roundtf(float f) { return __uint_as_float(f2tf32(f)); }

__device__ __forceinline__ void mma_tf32(float c[4], const uint32_t a[4], const uint32_t b[2]) {
    asm volatile(
        "mma.sync.aligned.m16n8k8.row.col.f32.tf32.tf32.f32 "
        "{%0,%1,%2,%3}, {%4,%5,%6,%7}, {%8,%9}, {%0,%1,%2,%3};\n"
        : "+f"(c[0]), "+f"(c[1]), "+f"(c[2]), "+f"(c[3])
        : "r"(a[0]), "r"(a[1]), "r"(a[2]), "r"(a[3]), "r"(b[0]), "r"(b[1]));
}

__device__ __forceinline__ void cp_async16(void* smem_dst, const void* gmem_src) {
    uint32_t s = (uint32_t)__cvta_generic_to_shared(smem_dst);
    asm volatile("cp.async.cg.shared.global [%0], [%1], 16;\n" :: "r"(s), "l"(gmem_src));
}
#define CP_COMMIT() asm volatile("cp.async.commit_group;\n" ::: "memory")
#define CP_WAIT(n)  asm volatile("cp.async.wait_group %0;\n" :: "n"(n) : "memory")

// ---------------------------------------------------------------------------
// Pre-round fp32 -> tf32 bit patterns (elementwise, float4)
// ---------------------------------------------------------------------------
__global__ __launch_bounds__(256) void preround_kernel(
    const float4* __restrict__ in, float4* __restrict__ out, int n4)
{
    int i = blockIdx.x * blockDim.x + threadIdx.x;
    if (i < n4) {
        float4 v = in[i];
        v.x = roundtf(v.x); v.y = roundtf(v.y);
        v.z = roundtf(v.z); v.w = roundtf(v.w);
        out[i] = v;
    }
}

// ---------------------------------------------------------------------------
// TF32 tensor-core GEMM + bias. Inputs PRE-ROUNDED tf32 bit patterns.
// BM=BN=128, BK=32. 128 threads = 4 warps (2m x 2n), warp tile 64x64.
// Replication: A x2, B x2 -> smem reads 64KB/ktile < tensor 2048cyc budget.
// 2 CTAs/SM. Double-buffered cp.async.
// ---------------------------------------------------------------------------
#define AS_STRIDE 36
#define BS_STRIDE 136
#define A_TILE_FLOATS (128 * AS_STRIDE)  // 4608
#define B_TILE_FLOATS (32 * BS_STRIDE)   // 4352

template <bool ROUND_OUT>
__global__ __launch_bounds__(128, 2) void tf32_gemm_bias_kernel(
    const float* __restrict__ A, const float* __restrict__ B,
    const float* __restrict__ bias, float* __restrict__ C,
    int M, int N, int K)
{
    extern __shared__ float sm[];
    float* As[2] = { sm, sm + A_TILE_FLOATS };
    float* Bs[2] = { sm + 2 * A_TILE_FLOATS, sm + 2 * A_TILE_FLOATS + B_TILE_FLOATS };

    const int tid  = threadIdx.x;
    const int lane = tid & 31, wid = tid >> 5;
    const int warp_m = wid >> 1;   // 0..1
    const int warp_n = wid & 1;    // 0..1
    const int gid = lane >> 2;     // 0..7
    const int tg  = lane & 3;      // 0..3

    const int bm = blockIdx.y * 128;
    const int bn = blockIdx.x * 128;

    // gmem->smem coordinates (128 threads, 8 passes each for A and B)
    const int a_row = tid >> 3;          // 0..15, +16 per pass
    const int a_col = (tid & 7) << 2;
    const int b_r0 = tid >> 5;           // 0..3, +4 per pass
    const int b_c0 = (tid & 31) << 2;

    const int ktiles = K >> 5;

    auto load_tile = [&](int buf, int kt) {
        const float* Ag = A + (size_t)(bm) * K + kt * 32;
        #pragma unroll
        for (int p = 0; p < 8; p++) {
            int r = a_row + 16 * p;
            cp_async16(&As[buf][r * AS_STRIDE + a_col], Ag + (size_t)r * K + a_col);
        }
        const float* Bg = B + (size_t)(kt * 32) * N + bn;
        #pragma unroll
        for (int p = 0; p < 8; p++) {
            int r = b_r0 + 4 * p;
            cp_async16(&Bs[buf][r * BS_STRIDE + b_c0], Bg + (size_t)r * N + b_c0);
        }
    };

    float acc[4][8][4];
    #pragma unroll
    for (int mt = 0; mt < 4; mt++)
        #pragma unroll
        for (int nt = 0; nt < 8; nt++)
            #pragma unroll
            for (int r = 0; r < 4; r++) acc[mt][nt][r] = 0.f;

    load_tile(0, 0);
    CP_COMMIT();

    for (int kt = 0; kt < ktiles; kt++) {
        const int cur = kt & 1;
        if (kt + 1 < ktiles) {
            load_tile(cur ^ 1, kt + 1);
            CP_COMMIT();
            CP_WAIT(1);
        } else {
            CP_WAIT(0);
        }
        __syncthreads();

        const float* as = As[cur];
        const float* bs = Bs[cur];

        #pragma unroll
        for (int ks = 0; ks < 4; ks++) {
            const int k8 = ks << 3;
            uint32_t af[4][4];
            #pragma unroll
            for (int mt = 0; mt < 4; mt++) {
                int r0 = warp_m * 64 + mt * 16 + gid;
                af[mt][0] = __float_as_uint(as[(r0    ) * AS_STRIDE + k8 + tg    ]);
                af[mt][1] = __float_as_uint(as[(r0 + 8) * AS_STRIDE + k8 + tg    ]);
                af[mt][2] = __float_as_uint(as[(r0    ) * AS_STRIDE + k8 + tg + 4]);
                af[mt][3] = __float_as_uint(as[(r0 + 8) * AS_STRIDE + k8 + tg + 4]);
            }
            uint32_t bf[8][2];
            #pragma unroll
            for (int nt = 0; nt < 8; nt++) {
                int c = warp_n * 64 + nt * 8 + gid;
                bf[nt][0] = __float_as_uint(bs[(k8 + tg    ) * BS_STRIDE + c]);
                bf[nt][1] = __float_as_uint(bs[(k8 + tg + 4) * BS_STRIDE + c]);
            }
            #pragma unroll
            for (int mt = 0; mt < 4; mt++)
                #pragma unroll
                for (int nt = 0; nt < 8; nt++)
                    mma_tf32(acc[mt][nt], af[mt], bf[nt]);
        }
        __syncthreads();
    }

    #pragma unroll
    for (int mt = 0; mt < 4; mt++) {
        #pragma unroll
        for (int nt = 0; nt < 8; nt++) {
            int r = bm + warp_m * 64 + mt * 16 + gid;
            int c = bn + warp_n * 64 + nt * 8 + (tg << 1);
            float b0 = bias[c], b1 = bias[c + 1];
            float2 v0, v1;
            if (ROUND_OUT) {
                v0 = make_float2(roundtf(acc[mt][nt][0] + b0), roundtf(acc[mt][nt][1] + b1));
                v1 = make_float2(roundtf(acc[mt][nt][2] + b0), roundtf(acc[mt][nt][3] + b1));
            } else {
                v0 = make_float2(acc[mt][nt][0] + b0, acc[mt][nt][1] + b1);
                v1 = make_float2(acc[mt][nt][2] + b0, acc[mt][nt][3] + b1);
            }
            *(float2*)(C + (size_t)r * N + c)       = v0;
            *(float2*)(C + (size_t)(r + 8) * N + c) = v1;
        }
    }
}

// ---------------------------------------------------------------------------
// Tensor-core flash attention. qkv is pre-rounded tf32 bit patterns.
// (unchanged from R5 passing version)
// ---------------------------------------------------------------------------
#define QS_ST 68
#define VS_ST 72
#define FL_SMEM_FLOATS (64 * QS_ST * 2 + 64 * VS_ST)  // 13312

__global__ __launch_bounds__(128) void flash_tc_kernel(
    const float* __restrict__ qkv, float* __restrict__ y)
{
    extern __shared__ float sm[];
    float* Qs  = sm;                       // [64][68]
    float* KPs = sm + 64 * QS_ST;          // [64][68]
    float* Vs  = sm + 2 * 64 * QS_ST;      // [64][72]

    const int qb = blockIdx.x, h = blockIdx.y, b = blockIdx.z;
    const int tid = threadIdx.x;
    const int lane = tid & 31, w = tid >> 5;
    const int gid = lane >> 2, tg = lane & 3;

    const size_t rs = (size_t)3 * Cc;
    const float* qbase = qkv + ((size_t)(b * Tt) + (size_t)qb * 64) * rs + h * Dd;

    #pragma unroll
    for (int it = 0; it < 8; it++) {
        int idx = tid + 128 * it;
        int r = idx >> 4, c = (idx & 15) << 2;
        cp_async16(&Qs[r * QS_ST + c], qbase + (size_t)r * rs + c);
    }
    CP_COMMIT();
    CP_WAIT(0);
    __syncthreads();

    uint32_t qa[8][4];
    {
        const int r0 = w * 16 + gid;
        #pragma unroll
        for (int kk = 0; kk < 8; kk++) {
            const int k8 = kk << 3;
            qa[kk][0] = __float_as_uint(Qs[(r0    ) * QS_ST + k8 + tg    ]);
            qa[kk][1] = __float_as_uint(Qs[(r0 + 8) * QS_ST + k8 + tg    ]);
            qa[kk][2] = __float_as_uint(Qs[(r0    ) * QS_ST + k8 + tg + 4]);
            qa[kk][3] = __float_as_uint(Qs[(r0 + 8) * QS_ST + k8 + tg + 4]);
        }
    }

    float o[8][4];
    #pragma unroll
    for (int nt = 0; nt < 8; nt++)
        #pragma unroll
        for (int r = 0; r < 4; r++) o[nt][r] = 0.f;
    float m0 = -INFINITY, m1 = -INFINITY, l0 = 0.f, l1 = 0.f;

    const float scale = 0.125f;

    for (int kb = 0; kb <= qb; kb++) {
        __syncthreads();

        const float* kbase = qkv + ((size_t)(b * Tt) + (size_t)kb * 64) * rs + Cc + h * Dd;
        const float* vbase = kbase + Cc;
        #pragma unroll
        for (int it = 0; it < 8; it++) {
            int idx = tid + 128 * it;
            int r = idx >> 4, c = (idx & 15) << 2;
            cp_async16(&KPs[r * QS_ST + c], kbase + (size_t)r * rs + c);
            cp_async16(&Vs [r * VS_ST + c], vbase + (size_t)r * rs + c);
        }
        CP_COMMIT();
        CP_WAIT(0);
        __syncthreads();

        // ---- S = Q K^T ----
        float s[8][4];
        #pragma unroll
        for (int nt = 0; nt < 8; nt++) {
            #pragma unroll
            for (int r = 0; r < 4; r++) s[nt][r] = 0.f;
            const int n = nt * 8 + gid;
            #pragma unroll
            for (int kk = 0; kk < 8; kk++) {
                const int k8 = kk << 3;
                uint32_t bf[2];
                bf[0] = __float_as_uint(KPs[n * QS_ST + k8 + tg    ]);
                bf[1] = __float_as_uint(KPs[n * QS_ST + k8 + tg + 4]);
                mma_tf32(s[nt], qa[kk], bf);
            }
        }

        // ---- scale + causal mask ----
        if (kb == qb) {
            const int ql0 = w * 16 + gid, ql1 = ql0 + 8;
            #pragma unroll
            for (int nt = 0; nt < 8; nt++) {
                const int kl = nt * 8 + (tg << 1);
                s[nt][0] = (kl     <= ql0) ? s[nt][0] * scale : -INFINITY;
                s[nt][1] = (kl + 1 <= ql0) ? s[nt][1] * scale : -INFINITY;
                s[nt][2] = (kl     <= ql1) ? s[nt][2] * scale : -INFINITY;
                s[nt][3] = (kl + 1 <= ql1) ? s[nt][3] * scale : -INFINITY;
            }
        } else {
            #pragma unroll
            for (int nt = 0; nt < 8; nt++)
                #pragma unroll
                for (int r = 0; r < 4; r++) s[nt][r] *= scale;
        }

        // ---- online softmax ----
        float mx0 = -INFINITY, mx1 = -INFINITY;
        #pragma unroll
        for (int nt = 0; nt < 8; nt++) {
            mx0 = fmaxf(mx0, fmaxf(s[nt][0], s[nt][1]));
            mx1 = fmaxf(mx1, fmaxf(s[nt][2], s[nt][3]));
        }
        mx0 = fmaxf(mx0, __shfl_xor_sync(0xffffffffu, mx0, 1));
        mx0 = fmaxf(mx0, __shfl_xor_sync(0xffffffffu, mx0, 2));
        mx1 = fmaxf(mx1, __shfl_xor_sync(0xffffffffu, mx1, 1));
        mx1 = fmaxf(mx1, __shfl_xor_sync(0xffffffffu, mx1, 2));

        const float nm0 = fmaxf(m0, mx0);
        const float nm1 = fmaxf(m1, mx1);
        const float a0 = __expf(m0 - nm0);
        const float a1 = __expf(m1 - nm1);
        m0 = nm0; m1 = nm1;

        float sum0 = 0.f, sum1 = 0.f;
        #pragma unroll
        for (int nt = 0; nt < 8; nt++) {
            s[nt][0] = __expf(s[nt][0] - nm0);
            s[nt][1] = __expf(s[nt][1] - nm0);
            s[nt][2] = __expf(s[nt][2] - nm1);
            s[nt][3] = __expf(s[nt][3] - nm1);
            sum0 += s[nt][0] + s[nt][1];
            sum1 += s[nt][2] + s[nt][3];
        }
        sum0 += __shfl_xor_sync(0xffffffffu, sum0, 1);
        sum0 += __shfl_xor_sync(0xffffffffu, sum0, 2);
        sum1 += __shfl_xor_sync(0xffffffffu, sum1, 1);
        sum1 += __shfl_xor_sync(0xffffffffu, sum1, 2);
        l0 = l0 * a0 + sum0;
        l1 = l1 * a1 + sum1;

        #pragma unroll
        for (int nt = 0; nt < 8; nt++) {
            o[nt][0] *= a0; o[nt][1] *= a0;
            o[nt][2] *= a1; o[nt][3] *= a1;
        }

        // ---- P -> smem (tf32-rounded at store) ----
        __syncthreads();
        {
            const int r0 = w * 16 + gid;
            #pragma unroll
            for (int nt = 0; nt < 8; nt++) {
                const int c = nt * 8 + (tg << 1);
                *(float2*)&KPs[(r0    ) * QS_ST + c] = make_float2(roundtf(s[nt][0]), roundtf(s[nt][1]));
                *(float2*)&KPs[(r0 + 8) * QS_ST + c] = make_float2(roundtf(s[nt][2]), roundtf(s[nt][3]));
            }
        }
        __syncthreads();

        // ---- O += P @ V ----
        uint32_t pa[8][4];
        {
            const int r0 = w * 16 + gid;
            #pragma unroll
            for (int kk = 0; kk < 8; kk++) {
                const int k8 = kk << 3;
                pa[kk][0] = __float_as_uint(KPs[(r0    ) * QS_ST + k8 + tg    ]);
                pa[kk][1] = __float_as_uint(KPs[(r0 + 8) * QS_ST + k8 + tg    ]);
                pa[kk][2] = __float_as_uint(KPs[(r0    ) * QS_ST + k8 + tg + 4]);
                pa[kk][3] = __float_as_uint(KPs[(r0 + 8) * QS_ST + k8 + tg + 4]);
            }
        }
        #pragma unroll
        for (int nt = 0; nt < 8; nt++) {
            const int n = nt * 8 + gid;
            #pragma unroll
            for (int kk = 0; kk < 8; kk++) {
                const int k8 = kk << 3;
                uint32_t bf[2];
                bf[0] = __float_as_uint(Vs[(k8 + tg    ) * VS_ST + n]);
                bf[1] = __float_as_uint(Vs[(k8 + tg + 4) * VS_ST + n]);
                mma_tf32(o[nt], pa[kk], bf);
            }
        }
    }

    // ---- normalize + write ----
    const float inv0 = 1.f / l0;
    const float inv1 = 1.f / l1;
    const int r0g = qb * 64 + w * 16 + gid;
    float* y0 = y + ((size_t)(b * Tt) + r0g) * Cc + h * Dd;
    float* y1 = y0 + 8 * Cc;
    #pragma unroll
    for (int nt = 0; nt < 8; nt++) {
        const int c = nt * 8 + (tg << 1);
        *(float2*)(y0 + c) = make_float2(roundtf(o[nt][0] * inv0), roundtf(o[nt][1] * inv0));
        *(float2*)(y1 + c) = make_float2(roundtf(o[nt][2] * inv1), roundtf(o[nt][3] * inv1));
    }
}

// ---------------------------------------------------------------------------
extern "C" void kernel_launch(void* const* d_in, const int* in_sizes, int n_in,
                              void* d_out, int out_size)
{
    const float* x  = (const float*)d_in[0];
    const float* Wa = (const float*)d_in[1];
    const float* ba = (const float*)d_in[2];
    const float* Wp = (const float*)d_in[3];
    const float* bp = (const float*)d_in[4];
    float* out = (float*)d_out;

    float *qkv, *y, *xr, *war, *wpr;
    cudaGetSymbolAddress((void**)&qkv, g_qkv);
    cudaGetSymbolAddress((void**)&y,   g_y);
    cudaGetSymbolAddress((void**)&xr,  g_xr);
    cudaGetSymbolAddress((void**)&war, g_war);
    cudaGetSymbolAddress((void**)&wpr, g_wpr);

    const int M = Bb * Tt;           // 8192
    const int N1 = 3 * Cc;           // 3072

    const int gemm_smem  = (2 * A_TILE_FLOATS + 2 * B_TILE_FLOATS) * (int)sizeof(float); // 71680
    const int flash_smem = FL_SMEM_FLOATS * (int)sizeof(float);                          // 53248
    cudaFuncSetAttribute(tf32_gemm_bias_kernel<true>,  cudaFuncAttributeMaxDynamicSharedMemorySize, gemm_smem);
    cudaFuncSetAttribute(tf32_gemm_bias_kernel<false>, cudaFuncAttributeMaxDynamicSharedMemorySize, gemm_smem);
    cudaFuncSetAttribute(flash_tc_kernel, cudaFuncAttributeMaxDynamicSharedMemorySize, flash_smem);

    // Pre-round inputs to tf32 bit patterns
    {
        int n4x = (M * Cc) / 4, n4a = (Cc * N1) / 4, n4p = (Cc * Cc) / 4;
        preround_kernel<<<(n4x + 255) / 256, 256>>>((const float4*)x,  (float4*)xr,  n4x);
        preround_kernel<<<(n4a + 255) / 256, 256>>>((const float4*)Wa, (float4*)war, n4a);
        preround_kernel<<<(n4p + 255) / 256, 256>>>((const float4*)Wp, (float4*)wpr, n4p);
    }

    // GEMM1: qkv = x @ W_attn + b_attn (output tf32-rounded)
    tf32_gemm_bias_kernel<true><<<dim3(N1 / 128, M / 128), 128, gemm_smem>>>(xr, war, ba, qkv, M, N1, Cc);

    // Flash attention (tensor-core)
    flash_tc_kernel<<<dim3(Tt / 64, Hh, Bb), 128, flash_smem>>>(qkv, y);

    // GEMM2: out = y @ W_proj + b_proj (final output, NOT rounded)
    tf32_gemm_bias_kernel<false><<<dim3(Cc / 128, M / 128), 128, gemm_smem>>>(y, wpr, bp, out, M, Cc, Cc);
}

// round 9
// speedup vs baseline: 7.7440x; 1.8912x over previous
#include <cuda_runtime.h>
#include <cuda_fp16.h>
#include <cstdint>
#include <math.h>

#define Bb 4
#define Tt 2048
#define Cc 1024
#define Hh 16
#define Dd 64

// Scratch (allocation-free rule: device globals), all fp16 now
__device__ __half g_qkv[(size_t)Bb * Tt * 3 * Cc];
__device__ __half g_y[(size_t)Bb * Tt * Cc];
__device__ __half g_xh[(size_t)Bb * Tt * Cc];     // x converted
__device__ __half g_wah[(size_t)Cc * 3 * Cc];     // W_attn^T [N][K] half
__device__ __half g_wph[(size_t)Cc * Cc];         // W_proj^T [N][K] half

// ---------------------------------------------------------------------------
// Helpers
// ---------------------------------------------------------------------------
__device__ __forceinline__ void mma_f16(float c[4],
    uint32_t a0, uint32_t a1, uint32_t a2, uint32_t a3, uint32_t b0, uint32_t b1)
{
    asm volatile(
        "mma.sync.aligned.m16n8k16.row.col.f32.f16.f16.f32 "
        "{%0,%1,%2,%3}, {%4,%5,%6,%7}, {%8,%9}, {%0,%1,%2,%3};\n"
        : "+f"(c[0]), "+f"(c[1]), "+f"(c[2]), "+f"(c[3])
        : "r"(a0), "r"(a1), "r"(a2), "r"(a3), "r"(b0), "r"(b1));
}

__device__ __forceinline__ void ldsm_x4(uint32_t& r0, uint32_t& r1, uint32_t& r2, uint32_t& r3, uint32_t a) {
    asm volatile("ldmatrix.sync.aligned.m8n8.x4.shared.b16 {%0,%1,%2,%3}, [%4];"
        : "=r"(r0), "=r"(r1), "=r"(r2), "=r"(r3) : "r"(a));
}
__device__ __forceinline__ void ldsm_x2_t(uint32_t& r0, uint32_t& r1, uint32_t a) {
    asm volatile("ldmatrix.sync.aligned.m8n8.x2.trans.shared.b16 {%0,%1}, [%2];"
        : "=r"(r0), "=r"(r1) : "r"(a));
}

__device__ __forceinline__ void cp_async16(void* smem_dst, const void* gmem_src) {
    uint32_t s = (uint32_t)__cvta_generic_to_shared(smem_dst);
    asm volatile("cp.async.cg.shared.global [%0], [%1], 16;\n" :: "r"(s), "l"(gmem_src));
}
#define CP_COMMIT() asm volatile("cp.async.commit_group;\n" ::: "memory")
#define CP_WAIT(n)  asm volatile("cp.async.wait_group %0;\n" :: "n"(n) : "memory")

__device__ __forceinline__ uint32_t cvta_s(const void* p) {
    return (uint32_t)__cvta_generic_to_shared(p);
}

__device__ __forceinline__ void store_pair(__half* p, float a, float b) {
    __half2 h = __floats2half2_rn(a, b);
    *(uint32_t*)p = *(uint32_t*)&h;
}
__device__ __forceinline__ void store_pair(float* p, float a, float b) {
    *(float2*)p = make_float2(a, b);
}

// ---------------------------------------------------------------------------
// fp32 -> fp16 conversion kernels
// ---------------------------------------------------------------------------
__global__ __launch_bounds__(256) void tohalf_kernel(
    const float4* __restrict__ in, uint2* __restrict__ out, int n4)
{
    int i = blockIdx.x * blockDim.x + threadIdx.x;
    if (i < n4) {
        float4 v = in[i];
        __half2 h0 = __floats2half2_rn(v.x, v.y);
        __half2 h1 = __floats2half2_rn(v.z, v.w);
        out[i] = make_uint2(*(uint32_t*)&h0, *(uint32_t*)&h1);
    }
}

// in [K][N] fp32 -> out [N][K] fp16
__global__ __launch_bounds__(256) void transpose_tohalf_kernel(
    const float* __restrict__ in, __half* __restrict__ out, int K, int N)
{
    __shared__ float t[32][33];
    int n0 = blockIdx.x * 32, k0 = blockIdx.y * 32;
    int tx = threadIdx.x & 31, ty = threadIdx.x >> 5;
    #pragma unroll
    for (int i = ty; i < 32; i += 8) t[i][tx] = in[(size_t)(k0 + i) * N + n0 + tx];
    __syncthreads();
    #pragma unroll
    for (int i = ty; i < 32; i += 8) out[(size_t)(n0 + i) * K + k0 + tx] = __float2half_rn(t[tx][i]);
}

// ---------------------------------------------------------------------------
// fp16 tensor-core GEMM + bias: C[M,N] = A[M,K] @ Bt[N,K]^T + bias[N]
// BM=BN=128, BK=32, 128 threads = 4 warps (2m x 2n), warp tile 64x64.
// Smem rows padded to 40 halves (word stride 20: gid*20+tg bijective mod 32).
// ---------------------------------------------------------------------------
#define GAS 40                       // halves per smem row
#define GTILE_H (128 * GAS)          // 5120 halves per operand tile
#define GSTAGE_H (2 * GTILE_H)       // 10240 halves per stage (A + B)
#define GEMM_SMEM (2 * GSTAGE_H * 2) // bytes: 40960

template <typename OutT>
__global__ __launch_bounds__(128, 2) void h_gemm_kernel(
    const __half* __restrict__ A, const __half* __restrict__ Bt,
    const float* __restrict__ bias, OutT* __restrict__ C,
    int M, int N, int K)
{
    extern __shared__ __half smh[];
    __half* As[2] = { smh,           smh + GSTAGE_H };
    __half* Bs[2] = { smh + GTILE_H, smh + GSTAGE_H + GTILE_H };

    const int tid = threadIdx.x;
    const int lane = tid & 31, wid = tid >> 5;
    const int warp_m = wid >> 1, warp_n = wid & 1;
    const int gid = lane >> 2, tg = lane & 3;

    const int bm = blockIdx.y * 128, bn = blockIdx.x * 128;
    const int nt_k = K >> 5;

    auto load_tile = [&](int buf, int kt) {
        const __half* Ag = A  + (size_t)bm * K + kt * 32;
        const __half* Bg = Bt + (size_t)bn * K + kt * 32;
        #pragma unroll
        for (int p = 0; p < 4; p++) {
            int idx = tid + 128 * p;
            int r = idx >> 2, c = (idx & 3) << 3;     // 8 halves = 16B
            cp_async16(&As[buf][r * GAS + c], Ag + (size_t)r * K + c);
            cp_async16(&Bs[buf][r * GAS + c], Bg + (size_t)r * K + c);
        }
    };

    float acc[4][8][4];
    #pragma unroll
    for (int mt = 0; mt < 4; mt++)
        #pragma unroll
        for (int nt = 0; nt < 8; nt++)
            #pragma unroll
            for (int r = 0; r < 4; r++) acc[mt][nt][r] = 0.f;

    load_tile(0, 0);
    CP_COMMIT();

    for (int kt = 0; kt < nt_k; kt++) {
        const int cur = kt & 1;
        if (kt + 1 < nt_k) { load_tile(cur ^ 1, kt + 1); CP_COMMIT(); CP_WAIT(1); }
        else               { CP_WAIT(0); }
        __syncthreads();

        const __half* as = As[cur];
        const __half* bs = Bs[cur];

        #pragma unroll
        for (int ks = 0; ks < 2; ks++) {
            const int k16 = ks << 4;
            uint32_t af[4][4];
            #pragma unroll
            for (int mt = 0; mt < 4; mt++) {
                int base = (warp_m * 64 + mt * 16 + gid) * GAS + k16 + 2 * tg;
                af[mt][0] = *(const uint32_t*)(as + base);
                af[mt][1] = *(const uint32_t*)(as + base + 8 * GAS);
                af[mt][2] = *(const uint32_t*)(as + base + 8);
                af[mt][3] = *(const uint32_t*)(as + base + 8 * GAS + 8);
            }
            uint32_t bf[8][2];
            #pragma unroll
            for (int nt = 0; nt < 8; nt++) {
                int base = (warp_n * 64 + nt * 8 + gid) * GAS + k16 + 2 * tg;
                bf[nt][0] = *(const uint32_t*)(bs + base);
                bf[nt][1] = *(const uint32_t*)(bs + base + 8);
            }
            #pragma unroll
            for (int mt = 0; mt < 4; mt++)
                #pragma unroll
                for (int nt = 0; nt < 8; nt++)
                    mma_f16(acc[mt][nt], af[mt][0], af[mt][1], af[mt][2], af[mt][3],
                            bf[nt][0], bf[nt][1]);
        }
        __syncthreads();
    }

    #pragma unroll
    for (int mt = 0; mt < 4; mt++) {
        #pragma unroll
        for (int nt = 0; nt < 8; nt++) {
            int r = bm + warp_m * 64 + mt * 16 + gid;
            int c = bn + warp_n * 64 + nt * 8 + (tg << 1);
            float b0 = bias[c], b1 = bias[c + 1];
            store_pair(C + (size_t)r * N + c,       acc[mt][nt][0] + b0, acc[mt][nt][1] + b1);
            store_pair(C + (size_t)(r + 8) * N + c, acc[mt][nt][2] + b0, acc[mt][nt][3] + b1);
        }
    }
}

// ---------------------------------------------------------------------------
// fp16 tensor-core flash attention (causal, online softmax).
// 128 threads = 4 warps; warp owns 16 Q rows. K/V double-buffered (cp.async
// prefetch). ldmatrix x4 for Q/K/P fragments, x2.trans for V.
// Smem (halves, stride 72): Q | K0 | K1 | V0 | V1 | P  = 6*4608 = 27648.
// ---------------------------------------------------------------------------
#define FST 72
#define FTILE_H (64 * FST)                  // 4608
#define FLASH_SMEM (6 * FTILE_H * 2)        // 55296 bytes

__global__ __launch_bounds__(128) void flash_h_kernel(
    const __half* __restrict__ qkv, __half* __restrict__ y)
{
    extern __shared__ __half sh[];
    __half* Qs    = sh;
    __half* Ks[2] = { sh + FTILE_H,     sh + 2 * FTILE_H };
    __half* Vs[2] = { sh + 3 * FTILE_H, sh + 4 * FTILE_H };
    __half* Ps    = sh + 5 * FTILE_H;

    const int qb = blockIdx.x, h = blockIdx.y, b = blockIdx.z;
    const int tid = threadIdx.x;
    const int lane = tid & 31, w = tid >> 5;
    const int gid = lane >> 2, tg = lane & 3;
    const int lj = lane & 7, lb = lane >> 3;

    const size_t rs = (size_t)3 * Cc;   // 3072 halves
    const __half* qbase = qkv + ((size_t)(b * Tt) + (size_t)qb * 64) * rs + h * Dd;

    auto load_kv = [&](int st, int kb) {
        const __half* kbase = qkv + ((size_t)(b * Tt) + (size_t)kb * 64) * rs + Cc + h * Dd;
        const __half* vbase = kbase + Cc;
        #pragma unroll
        for (int p = 0; p < 4; p++) {
            int idx = tid + 128 * p;
            int r = idx >> 3, c = (idx & 7) << 3;
            cp_async16(&Ks[st][r * FST + c], kbase + (size_t)r * rs + c);
            cp_async16(&Vs[st][r * FST + c], vbase + (size_t)r * rs + c);
        }
    };

    // Q + first K/V
    #pragma unroll
    for (int p = 0; p < 4; p++) {
        int idx = tid + 128 * p;
        int r = idx >> 3, c = (idx & 7) << 3;
        cp_async16(&Qs[r * FST + c], qbase + (size_t)r * rs + c);
    }
    load_kv(0, 0);
    CP_COMMIT();
    CP_WAIT(0);
    __syncthreads();

    // Q A-fragments via ldmatrix.x4 (row = rbase + (lb&1)*8 + lj, k = kk*16 + (lb>>1)*8)
    uint32_t qa[4][4];
    {
        const int arow = w * 16 + (lb & 1) * 8 + lj;
        const int akof = (lb >> 1) * 8;
        #pragma unroll
        for (int kk = 0; kk < 4; kk++)
            ldsm_x4(qa[kk][0], qa[kk][1], qa[kk][2], qa[kk][3],
                    cvta_s(&Qs[arow * FST + kk * 16 + akof]));
    }

    float o[8][4];
    #pragma unroll
    for (int nt = 0; nt < 8; nt++)
        #pragma unroll
        for (int r = 0; r < 4; r++) o[nt][r] = 0.f;
    float m0 = -INFINITY, m1 = -INFINITY, l0 = 0.f, l1 = 0.f;
    const float scale = 0.125f;

    for (int kb = 0; kb <= qb; kb++) {
        const int cur = kb & 1;
        if (kb < qb) { load_kv(cur ^ 1, kb + 1); CP_COMMIT(); }   // prefetch

        // ---- S = Q K^T ----
        float s[8][4];
        #pragma unroll
        for (int nt = 0; nt < 8; nt++)
            #pragma unroll
            for (int r = 0; r < 4; r++) s[nt][r] = 0.f;

        {
            const __half* Kc = Ks[cur];
            // B-frags for 2 n-blocks per ldmatrix.x4:
            // row = (nt2 + (lb>>1))*8 + lj, k = kk*16 + (lb&1)*8
            const int brow8 = (lb >> 1) * 8 + lj;
            const int bkof  = (lb & 1) * 8;
            #pragma unroll
            for (int nt2 = 0; nt2 < 8; nt2 += 2) {
                #pragma unroll
                for (int kk = 0; kk < 4; kk++) {
                    uint32_t b0, b1, b2, b3;
                    ldsm_x4(b0, b1, b2, b3,
                            cvta_s(&Kc[(nt2 * 8 + brow8) * FST + kk * 16 + bkof]));
                    mma_f16(s[nt2],     qa[kk][0], qa[kk][1], qa[kk][2], qa[kk][3], b0, b1);
                    mma_f16(s[nt2 + 1], qa[kk][0], qa[kk][1], qa[kk][2], qa[kk][3], b2, b3);
                }
            }
        }

        // ---- scale + causal mask ----
        if (kb == qb) {
            const int ql0 = w * 16 + gid, ql1 = ql0 + 8;
            #pragma unroll
            for (int nt = 0; nt < 8; nt++) {
                const int kl = nt * 8 + (tg << 1);
                s[nt][0] = (kl     <= ql0) ? s[nt][0] * scale : -INFINITY;
                s[nt][1] = (kl + 1 <= ql0) ? s[nt][1] * scale : -INFINITY;
                s[nt][2] = (kl     <= ql1) ? s[nt][2] * scale : -INFINITY;
                s[nt][3] = (kl + 1 <= ql1) ? s[nt][3] * scale : -INFINITY;
            }
        } else {
            #pragma unroll
            for (int nt = 0; nt < 8; nt++)
                #pragma unroll
                for (int r = 0; r < 4; r++) s[nt][r] *= scale;
        }

        // ---- online softmax (rows gid / gid+8; reduce across tg lanes) ----
        float mx0 = -INFINITY, mx1 = -INFINITY;
        #pragma unroll
        for (int nt = 0; nt < 8; nt++) {
            mx0 = fmaxf(mx0, fmaxf(s[nt][0], s[nt][1]));
            mx1 = fmaxf(mx1, fmaxf(s[nt][2], s[nt][3]));
        }
        mx0 = fmaxf(mx0, __shfl_xor_sync(0xffffffffu, mx0, 1));
        mx0 = fmaxf(mx0, __shfl_xor_sync(0xffffffffu, mx0, 2));
        mx1 = fmaxf(mx1, __shfl_xor_sync(0xffffffffu, mx1, 1));
        mx1 = fmaxf(mx1, __shfl_xor_sync(0xffffffffu, mx1, 2));

        const float nm0 = fmaxf(m0, mx0);
        const float nm1 = fmaxf(m1, mx1);
        const float a0 = __expf(m0 - nm0);
        const float a1 = __expf(m1 - nm1);
        m0 = nm0; m1 = nm1;

        float sum0 = 0.f, sum1 = 0.f;
        #pragma unroll
        for (int nt = 0; nt < 8; nt++) {
            s[nt][0] = __expf(s[nt][0] - nm0);
            s[nt][1] = __expf(s[nt][1] - nm0);
            s[nt][2] = __expf(s[nt][2] - nm1);
            s[nt][3] = __expf(s[nt][3] - nm1);
            sum0 += s[nt][0] + s[nt][1];
            sum1 += s[nt][2] + s[nt][3];
        }
        sum0 += __shfl_xor_sync(0xffffffffu, sum0, 1);
        sum0 += __shfl_xor_sync(0xffffffffu, sum0, 2);
        sum1 += __shfl_xor_sync(0xffffffffu, sum1, 1);
        sum1 += __shfl_xor_sync(0xffffffffu, sum1, 2);
        l0 = l0 * a0 + sum0;
        l1 = l1 * a1 + sum1;

        #pragma unroll
        for (int nt = 0; nt < 8; nt++) {
            o[nt][0] *= a0; o[nt][1] *= a0;
            o[nt][2] *= a1; o[nt][3] *= a1;
        }

        // ---- P -> smem (fp16). Prior iteration fully done (end-of-iter sync). ----
        {
            const int r0 = w * 16 + gid;
            #pragma unroll
            for (int nt = 0; nt < 8; nt++) {
                const int c = nt * 8 + (tg << 1);
                store_pair(&Ps[(r0    ) * FST + c], s[nt][0], s[nt][1]);
                store_pair(&Ps[(r0 + 8) * FST + c], s[nt][2], s[nt][3]);
            }
        }
        __syncthreads();

        // ---- O += P @ V ----
        uint32_t pa[4][4];
        {
            const int arow = w * 16 + (lb & 1) * 8 + lj;
            const int akof = (lb >> 1) * 8;
            #pragma unroll
            for (int kk = 0; kk < 4; kk++)
                ldsm_x4(pa[kk][0], pa[kk][1], pa[kk][2], pa[kk][3],
                        cvta_s(&Ps[arow * FST + kk * 16 + akof]));
        }
        {
            const __half* Vc = Vs[cur];
            const int vrow8 = ((lane >> 3) & 1) * 8 + lj;   // k-row within 16-block
            #pragma unroll
            for (int nt = 0; nt < 8; nt++) {
                #pragma unroll
                for (int kk = 0; kk < 4; kk++) {
                    uint32_t b0, b1;
                    ldsm_x2_t(b0, b1, cvta_s(&Vc[(kk * 16 + vrow8) * FST + nt * 8]));
                    mma_f16(o[nt], pa[kk][0], pa[kk][1], pa[kk][2], pa[kk][3], b0, b1);
                }
            }
        }

        if (kb < qb) { CP_WAIT(0); __syncthreads(); }   // next K/V ready; all done with cur
    }

    // ---- normalize + write y (half) ----
    const float inv0 = 1.f / l0;
    const float inv1 = 1.f / l1;
    const int r0g = qb * 64 + w * 16 + gid;
    __half* y0 = y + ((size_t)(b * Tt) + r0g) * Cc + h * Dd;
    __half* y1 = y0 + 8 * Cc;
    #pragma unroll
    for (int nt = 0; nt < 8; nt++) {
        const int c = nt * 8 + (tg << 1);
        store_pair(y0 + c, o[nt][0] * inv0, o[nt][1] * inv0);
        store_pair(y1 + c, o[nt][2] * inv1, o[nt][3] * inv1);
    }
}

// ---------------------------------------------------------------------------
extern "C" void kernel_launch(void* const* d_in, const int* in_sizes, int n_in,
                              void* d_out, int out_size)
{
    const float* x  = (const float*)d_in[0];
    const float* Wa = (const float*)d_in[1];
    const float* ba = (const float*)d_in[2];
    const float* Wp = (const float*)d_in[3];
    const float* bp = (const float*)d_in[4];
    float* out = (float*)d_out;

    __half *qkv, *y, *xh, *wah, *wph;
    cudaGetSymbolAddress((void**)&qkv, g_qkv);
    cudaGetSymbolAddress((void**)&y,   g_y);
    cudaGetSymbolAddress((void**)&xh,  g_xh);
    cudaGetSymbolAddress((void**)&wah, g_wah);
    cudaGetSymbolAddress((void**)&wph, g_wph);

    const int M = Bb * Tt;           // 8192
    const int N1 = 3 * Cc;           // 3072

    cudaFuncSetAttribute(h_gemm_kernel<__half>, cudaFuncAttributeMaxDynamicSharedMemorySize, GEMM_SMEM);
    cudaFuncSetAttribute(h_gemm_kernel<float>,  cudaFuncAttributeMaxDynamicSharedMemorySize, GEMM_SMEM);
    cudaFuncSetAttribute(flash_h_kernel, cudaFuncAttributeMaxDynamicSharedMemorySize, FLASH_SMEM);

    // Convert x to half; transpose+convert weights to [N][K] half
    {
        int n4x = (M * Cc) / 4;
        tohalf_kernel<<<(n4x + 255) / 256, 256>>>((const float4*)x, (uint2*)xh, n4x);
        transpose_tohalf_kernel<<<dim3(N1 / 32, Cc / 32), 256>>>(Wa, wah, Cc, N1);
        transpose_tohalf_kernel<<<dim3(Cc / 32, Cc / 32), 256>>>(Wp, wph, Cc, Cc);
    }

    // GEMM1: qkv = x @ W_attn + b_attn  (half out)
    h_gemm_kernel<__half><<<dim3(N1 / 128, M / 128), 128, GEMM_SMEM>>>(xh, wah, ba, qkv, M, N1, Cc);

    // Flash attention (fp16 tensor cores)
    flash_h_kernel<<<dim3(Tt / 64, Hh, Bb), 128, FLASH_SMEM>>>(qkv, y);

    // GEMM2: out = y @ W_proj + b_proj  (fp32 out, final)
    h_gemm_kernel<float><<<dim3(Cc / 128, M / 128), 128, GEMM_SMEM>>>(y, wph, bp, out, M, Cc, Cc);
}

// round 10
// speedup vs baseline: 8.7241x; 1.1266x over previous
#include <cuda_runtime.h>
#include <cuda_fp16.h>
#include <cstdint>
#include <math.h>

#define Bb 4
#define Tt 2048
#define Cc 1024
#define Hh 16
#define Dd 64

// Scratch (allocation-free rule: device globals), all fp16
__device__ __half g_qkv[(size_t)Bb * Tt * 3 * Cc];
__device__ __half g_y[(size_t)Bb * Tt * Cc];
__device__ __half g_xh[(size_t)Bb * Tt * Cc];     // x converted
__device__ __half g_wah[(size_t)Cc * 3 * Cc];     // W_attn^T [N][K] half
__device__ __half g_wph[(size_t)Cc * Cc];         // W_proj^T [N][K] half

// ---------------------------------------------------------------------------
// Helpers
// ---------------------------------------------------------------------------
__device__ __forceinline__ void mma_f16(float c[4],
    uint32_t a0, uint32_t a1, uint32_t a2, uint32_t a3, uint32_t b0, uint32_t b1)
{
    asm volatile(
        "mma.sync.aligned.m16n8k16.row.col.f32.f16.f16.f32 "
        "{%0,%1,%2,%3}, {%4,%5,%6,%7}, {%8,%9}, {%0,%1,%2,%3};\n"
        : "+f"(c[0]), "+f"(c[1]), "+f"(c[2]), "+f"(c[3])
        : "r"(a0), "r"(a1), "r"(a2), "r"(a3), "r"(b0), "r"(b1));
}

__device__ __forceinline__ void ldsm_x4(uint32_t& r0, uint32_t& r1, uint32_t& r2, uint32_t& r3, uint32_t a) {
    asm volatile("ldmatrix.sync.aligned.m8n8.x4.shared.b16 {%0,%1,%2,%3}, [%4];"
        : "=r"(r0), "=r"(r1), "=r"(r2), "=r"(r3) : "r"(a));
}
__device__ __forceinline__ void ldsm_x2_t(uint32_t& r0, uint32_t& r1, uint32_t a) {
    asm volatile("ldmatrix.sync.aligned.m8n8.x2.trans.shared.b16 {%0,%1}, [%2];"
        : "=r"(r0), "=r"(r1) : "r"(a));
}

__device__ __forceinline__ void cp_async16(void* smem_dst, const void* gmem_src) {
    uint32_t s = (uint32_t)__cvta_generic_to_shared(smem_dst);
    asm volatile("cp.async.cg.shared.global [%0], [%1], 16;\n" :: "r"(s), "l"(gmem_src));
}
#define CP_COMMIT() asm volatile("cp.async.commit_group;\n" ::: "memory")
#define CP_WAIT(n)  asm volatile("cp.async.wait_group %0;\n" :: "n"(n) : "memory")

__device__ __forceinline__ uint32_t cvta_s(const void* p) {
    return (uint32_t)__cvta_generic_to_shared(p);
}

__device__ __forceinline__ void store_pair(__half* p, float a, float b) {
    __half2 h = __floats2half2_rn(a, b);
    *(uint32_t*)p = *(uint32_t*)&h;
}
__device__ __forceinline__ void store_pair(float* p, float a, float b) {
    *(float2*)p = make_float2(a, b);
}

// ---------------------------------------------------------------------------
// fp32 -> fp16 conversion kernels
// ---------------------------------------------------------------------------
__global__ __launch_bounds__(256) void tohalf_kernel(
    const float4* __restrict__ in, uint2* __restrict__ out, int n4)
{
    int i = blockIdx.x * blockDim.x + threadIdx.x;
    if (i < n4) {
        float4 v = in[i];
        __half2 h0 = __floats2half2_rn(v.x, v.y);
        __half2 h1 = __floats2half2_rn(v.z, v.w);
        out[i] = make_uint2(*(uint32_t*)&h0, *(uint32_t*)&h1);
    }
}

// in [K][N] fp32 -> out [N][K] fp16
__global__ __launch_bounds__(256) void transpose_tohalf_kernel(
    const float* __restrict__ in, __half* __restrict__ out, int K, int N)
{
    __shared__ float t[32][33];
    int n0 = blockIdx.x * 32, k0 = blockIdx.y * 32;
    int tx = threadIdx.x & 31, ty = threadIdx.x >> 5;
    #pragma unroll
    for (int i = ty; i < 32; i += 8) t[i][tx] = in[(size_t)(k0 + i) * N + n0 + tx];
    __syncthreads();
    #pragma unroll
    for (int i = ty; i < 32; i += 8) out[(size_t)(n0 + i) * K + k0 + tx] = __float2half_rn(t[tx][i]);
}

// ---------------------------------------------------------------------------
// fp16 tensor-core GEMM + bias: C[M,N] = A[M,K] @ Bt[N,K]^T + bias[N]
// BM=BN=128, BK=64. 128 threads = 4 warps (2m x 2n), warp tile 64x64.
// ldmatrix.x4 fragments; smem stride 72 halves (36 words -> 4r bank groups,
// conflict-free for ldmatrix). Double-buffered cp.async.
// ---------------------------------------------------------------------------
#define GAS 72                        // halves per smem row (64 + 8 pad)
#define GTILE_H (128 * GAS)           // 9216 halves per operand tile
#define GSTAGE_H (2 * GTILE_H)        // A + B per stage
#define GEMM_SMEM (2 * GSTAGE_H * 2)  // bytes: 73728

template <typename OutT>
__global__ __launch_bounds__(128, 2) void h_gemm_kernel(
    const __half* __restrict__ A, const __half* __restrict__ Bt,
    const float* __restrict__ bias, OutT* __restrict__ C,
    int M, int N, int K)
{
    extern __shared__ __half smh[];
    __half* As[2] = { smh,           smh + GSTAGE_H };
    __half* Bs[2] = { smh + GTILE_H, smh + GSTAGE_H + GTILE_H };

    const int tid = threadIdx.x;
    const int lane = tid & 31, wid = tid >> 5;
    const int warp_m = wid >> 1, warp_n = wid & 1;
    const int gid = lane >> 2, tg = lane & 3;
    const int lj = lane & 7, lb = lane >> 3;

    const int bm = blockIdx.y * 128, bn = blockIdx.x * 128;
    const int nt_k = K >> 6;   // ktiles of 64

    auto load_tile = [&](int buf, int kt) {
        const __half* Ag = A  + (size_t)bm * K + kt * 64;
        const __half* Bg = Bt + (size_t)bn * K + kt * 64;
        #pragma unroll
        for (int p = 0; p < 8; p++) {
            int idx = tid + 128 * p;
            int r = idx >> 3, c = (idx & 7) << 3;     // 8 halves = 16B
            cp_async16(&As[buf][r * GAS + c], Ag + (size_t)r * K + c);
            cp_async16(&Bs[buf][r * GAS + c], Bg + (size_t)r * K + c);
        }
    };

    float acc[4][8][4];
    #pragma unroll
    for (int mt = 0; mt < 4; mt++)
        #pragma unroll
        for (int nt = 0; nt < 8; nt++)
            #pragma unroll
            for (int r = 0; r < 4; r++) acc[mt][nt][r] = 0.f;

    load_tile(0, 0);
    CP_COMMIT();

    // ldmatrix address components (same pattern as validated flash kernel)
    const int a_row_off = (lb & 1) * 8 + lj;   // within 16-row block
    const int a_col_off = (lb >> 1) * 8;       // within 16-col (k) block
    const int b_row_off = (lb >> 1) * 8 + lj;
    const int b_col_off = (lb & 1) * 8;

    for (int kt = 0; kt < nt_k; kt++) {
        const int cur = kt & 1;
        if (kt + 1 < nt_k) { load_tile(cur ^ 1, kt + 1); CP_COMMIT(); CP_WAIT(1); }
        else               { CP_WAIT(0); }
        __syncthreads();

        const __half* as = As[cur];
        const __half* bs = Bs[cur];

        #pragma unroll
        for (int kk = 0; kk < 4; kk++) {     // 4 x k16 per ktile
            const int k16 = kk << 4;
            uint32_t af[4][4];
            #pragma unroll
            for (int mt = 0; mt < 4; mt++) {
                const int r = warp_m * 64 + mt * 16 + a_row_off;
                ldsm_x4(af[mt][0], af[mt][1], af[mt][2], af[mt][3],
                        cvta_s(&as[r * GAS + k16 + a_col_off]));
            }
            uint32_t bf[8][2];
            #pragma unroll
            for (int np = 0; np < 4; np++) {  // each x4 covers two n8 blocks
                const int r = warp_n * 64 + np * 16 + b_row_off;
                ldsm_x4(bf[2 * np][0], bf[2 * np][1], bf[2 * np + 1][0], bf[2 * np + 1][1],
                        cvta_s(&bs[r * GAS + k16 + b_col_off]));
            }
            #pragma unroll
            for (int mt = 0; mt < 4; mt++)
                #pragma unroll
                for (int nt = 0; nt < 8; nt++)
                    mma_f16(acc[mt][nt], af[mt][0], af[mt][1], af[mt][2], af[mt][3],
                            bf[nt][0], bf[nt][1]);
        }
        __syncthreads();
    }

    #pragma unroll
    for (int mt = 0; mt < 4; mt++) {
        #pragma unroll
        for (int nt = 0; nt < 8; nt++) {
            int r = bm + warp_m * 64 + mt * 16 + gid;
            int c = bn + warp_n * 64 + nt * 8 + (tg << 1);
            float b0 = bias[c], b1 = bias[c + 1];
            store_pair(C + (size_t)r * N + c,       acc[mt][nt][0] + b0, acc[mt][nt][1] + b1);
            store_pair(C + (size_t)(r + 8) * N + c, acc[mt][nt][2] + b0, acc[mt][nt][3] + b1);
        }
    }
}

// ---------------------------------------------------------------------------
// fp16 tensor-core flash attention (unchanged from R9 passing version).
// ---------------------------------------------------------------------------
#define FST 72
#define FTILE_H (64 * FST)                  // 4608
#define FLASH_SMEM (6 * FTILE_H * 2)        // 55296 bytes

__global__ __launch_bounds__(128) void flash_h_kernel(
    const __half* __restrict__ qkv, __half* __restrict__ y)
{
    extern __shared__ __half sh[];
    __half* Qs    = sh;
    __half* Ks[2] = { sh + FTILE_H,     sh + 2 * FTILE_H };
    __half* Vs[2] = { sh + 3 * FTILE_H, sh + 4 * FTILE_H };
    __half* Ps    = sh + 5 * FTILE_H;

    const int qb = blockIdx.x, h = blockIdx.y, b = blockIdx.z;
    const int tid = threadIdx.x;
    const int lane = tid & 31, w = tid >> 5;
    const int gid = lane >> 2, tg = lane & 3;
    const int lj = lane & 7, lb = lane >> 3;

    const size_t rs = (size_t)3 * Cc;   // 3072 halves
    const __half* qbase = qkv + ((size_t)(b * Tt) + (size_t)qb * 64) * rs + h * Dd;

    auto load_kv = [&](int st, int kb) {
        const __half* kbase = qkv + ((size_t)(b * Tt) + (size_t)kb * 64) * rs + Cc + h * Dd;
        const __half* vbase = kbase + Cc;
        #pragma unroll
        for (int p = 0; p < 4; p++) {
            int idx = tid + 128 * p;
            int r = idx >> 3, c = (idx & 7) << 3;
            cp_async16(&Ks[st][r * FST + c], kbase + (size_t)r * rs + c);
            cp_async16(&Vs[st][r * FST + c], vbase + (size_t)r * rs + c);
        }
    };

    #pragma unroll
    for (int p = 0; p < 4; p++) {
        int idx = tid + 128 * p;
        int r = idx >> 3, c = (idx & 7) << 3;
        cp_async16(&Qs[r * FST + c], qbase + (size_t)r * rs + c);
    }
    load_kv(0, 0);
    CP_COMMIT();
    CP_WAIT(0);
    __syncthreads();

    uint32_t qa[4][4];
    {
        const int arow = w * 16 + (lb & 1) * 8 + lj;
        const int akof = (lb >> 1) * 8;
        #pragma unroll
        for (int kk = 0; kk < 4; kk++)
            ldsm_x4(qa[kk][0], qa[kk][1], qa[kk][2], qa[kk][3],
                    cvta_s(&Qs[arow * FST + kk * 16 + akof]));
    }

    float o[8][4];
    #pragma unroll
    for (int nt = 0; nt < 8; nt++)
        #pragma unroll
        for (int r = 0; r < 4; r++) o[nt][r] = 0.f;
    float m0 = -INFINITY, m1 = -INFINITY, l0 = 0.f, l1 = 0.f;
    const float scale = 0.125f;

    for (int kb = 0; kb <= qb; kb++) {
        const int cur = kb & 1;
        if (kb < qb) { load_kv(cur ^ 1, kb + 1); CP_COMMIT(); }

        float s[8][4];
        #pragma unroll
        for (int nt = 0; nt < 8; nt++)
            #pragma unroll
            for (int r = 0; r < 4; r++) s[nt][r] = 0.f;

        {
            const __half* Kc = Ks[cur];
            const int brow8 = (lb >> 1) * 8 + lj;
            const int bkof  = (lb & 1) * 8;
            #pragma unroll
            for (int nt2 = 0; nt2 < 8; nt2 += 2) {
                #pragma unroll
                for (int kk = 0; kk < 4; kk++) {
                    uint32_t b0, b1, b2, b3;
                    ldsm_x4(b0, b1, b2, b3,
                            cvta_s(&Kc[(nt2 * 8 + brow8) * FST + kk * 16 + bkof]));
                    mma_f16(s[nt2],     qa[kk][0], qa[kk][1], qa[kk][2], qa[kk][3], b0, b1);
                    mma_f16(s[nt2 + 1], qa[kk][0], qa[kk][1], qa[kk][2], qa[kk][3], b2, b3);
                }
            }
        }

        if (kb == qb) {
            const int ql0 = w * 16 + gid, ql1 = ql0 + 8;
            #pragma unroll
            for (int nt = 0; nt < 8; nt++) {
                const int kl = nt * 8 + (tg << 1);
                s[nt][0] = (kl     <= ql0) ? s[nt][0] * scale : -INFINITY;
                s[nt][1] = (kl + 1 <= ql0) ? s[nt][1] * scale : -INFINITY;
                s[nt][2] = (kl     <= ql1) ? s[nt][2] * scale : -INFINITY;
                s[nt][3] = (kl + 1 <= ql1) ? s[nt][3] * scale : -INFINITY;
            }
        } else {
            #pragma unroll
            for (int nt = 0; nt < 8; nt++)
                #pragma unroll
                for (int r = 0; r < 4; r++) s[nt][r] *= scale;
        }

        float mx0 = -INFINITY, mx1 = -INFINITY;
        #pragma unroll
        for (int nt = 0; nt < 8; nt++) {
            mx0 = fmaxf(mx0, fmaxf(s[nt][0], s[nt][1]));
            mx1 = fmaxf(mx1, fmaxf(s[nt][2], s[nt][3]));
        }
        mx0 = fmaxf(mx0, __shfl_xor_sync(0xffffffffu, mx0, 1));
        mx0 = fmaxf(mx0, __shfl_xor_sync(0xffffffffu, mx0, 2));
        mx1 = fmaxf(mx1, __shfl_xor_sync(0xffffffffu, mx1, 1));
        mx1 = fmaxf(mx1, __shfl_xor_sync(0xffffffffu, mx1, 2));

        const float nm0 = fmaxf(m0, mx0);
        const float nm1 = fmaxf(m1, mx1);
        const float a0 = __expf(m0 - nm0);
        const float a1 = __expf(m1 - nm1);
        m0 = nm0; m1 = nm1;

        float sum0 = 0.f, sum1 = 0.f;
        #pragma unroll
        for (int nt = 0; nt < 8; nt++) {
            s[nt][0] = __expf(s[nt][0] - nm0);
            s[nt][1] = __expf(s[nt][1] - nm0);
            s[nt][2] = __expf(s[nt][2] - nm1);
            s[nt][3] = __expf(s[nt][3] - nm1);
            sum0 += s[nt][0] + s[nt][1];
            sum1 += s[nt][2] + s[nt][3];
        }
        sum0 += __shfl_xor_sync(0xffffffffu, sum0, 1);
        sum0 += __shfl_xor_sync(0xffffffffu, sum0, 2);
        sum1 += __shfl_xor_sync(0xffffffffu, sum1, 1);
        sum1 += __shfl_xor_sync(0xffffffffu, sum1, 2);
        l0 = l0 * a0 + sum0;
        l1 = l1 * a1 + sum1;

        #pragma unroll
        for (int nt = 0; nt < 8; nt++) {
            o[nt][0] *= a0; o[nt][1] *= a0;
            o[nt][2] *= a1; o[nt][3] *= a1;
        }

        {
            const int r0 = w * 16 + gid;
            #pragma unroll
            for (int nt = 0; nt < 8; nt++) {
                const int c = nt * 8 + (tg << 1);
                store_pair(&Ps[(r0    ) * FST + c], s[nt][0], s[nt][1]);
                store_pair(&Ps[(r0 + 8) * FST + c], s[nt][2], s[nt][3]);
            }
        }
        __syncthreads();

        uint32_t pa[4][4];
        {
            const int arow = w * 16 + (lb & 1) * 8 + lj;
            const int akof = (lb >> 1) * 8;
            #pragma unroll
            for (int kk = 0; kk < 4; kk++)
                ldsm_x4(pa[kk][0], pa[kk][1], pa[kk][2], pa[kk][3],
                        cvta_s(&Ps[arow * FST + kk * 16 + akof]));
        }
        {
            const __half* Vc = Vs[cur];
            const int vrow8 = ((lane >> 3) & 1) * 8 + lj;
            #pragma unroll
            for (int nt = 0; nt < 8; nt++) {
                #pragma unroll
                for (int kk = 0; kk < 4; kk++) {
                    uint32_t b0, b1;
                    ldsm_x2_t(b0, b1, cvta_s(&Vc[(kk * 16 + vrow8) * FST + nt * 8]));
                    mma_f16(o[nt], pa[kk][0], pa[kk][1], pa[kk][2], pa[kk][3], b0, b1);
                }
            }
        }

        if (kb < qb) { CP_WAIT(0); __syncthreads(); }
    }

    const float inv0 = 1.f / l0;
    const float inv1 = 1.f / l1;
    const int r0g = qb * 64 + w * 16 + gid;
    __half* y0 = y + ((size_t)(b * Tt) + r0g) * Cc + h * Dd;
    __half* y1 = y0 + 8 * Cc;
    #pragma unroll
    for (int nt = 0; nt < 8; nt++) {
        const int c = nt * 8 + (tg << 1);
        store_pair(y0 + c, o[nt][0] * inv0, o[nt][1] * inv0);
        store_pair(y1 + c, o[nt][2] * inv1, o[nt][3] * inv1);
    }
}

// ---------------------------------------------------------------------------
extern "C" void kernel_launch(void* const* d_in, const int* in_sizes, int n_in,
                              void* d_out, int out_size)
{
    const float* x  = (const float*)d_in[0];
    const float* Wa = (const float*)d_in[1];
    const float* ba = (const float*)d_in[2];
    const float* Wp = (const float*)d_in[3];
    const float* bp = (const float*)d_in[4];
    float* out = (float*)d_out;

    __half *qkv, *y, *xh, *wah, *wph;
    cudaGetSymbolAddress((void**)&qkv, g_qkv);
    cudaGetSymbolAddress((void**)&y,   g_y);
    cudaGetSymbolAddress((void**)&xh,  g_xh);
    cudaGetSymbolAddress((void**)&wah, g_wah);
    cudaGetSymbolAddress((void**)&wph, g_wph);

    const int M = Bb * Tt;           // 8192
    const int N1 = 3 * Cc;           // 3072

    cudaFuncSetAttribute(h_gemm_kernel<__half>, cudaFuncAttributeMaxDynamicSharedMemorySize, GEMM_SMEM);
    cudaFuncSetAttribute(h_gemm_kernel<float>,  cudaFuncAttributeMaxDynamicSharedMemorySize, GEMM_SMEM);
    cudaFuncSetAttribute(flash_h_kernel, cudaFuncAttributeMaxDynamicSharedMemorySize, FLASH_SMEM);

    {
        int n4x = (M * Cc) / 4;
        tohalf_kernel<<<(n4x + 255) / 256, 256>>>((const float4*)x, (uint2*)xh, n4x);
        transpose_tohalf_kernel<<<dim3(N1 / 32, Cc / 32), 256>>>(Wa, wah, Cc, N1);
        transpose_tohalf_kernel<<<dim3(Cc / 32, Cc / 32), 256>>>(Wp, wph, Cc, Cc);
    }

    // GEMM1: qkv = x @ W_attn + b_attn  (half out)
    h_gemm_kernel<__half><<<dim3(N1 / 128, M / 128), 128, GEMM_SMEM>>>(xh, wah, ba, qkv, M, N1, Cc);

    // Flash attention (fp16 tensor cores)
    flash_h_kernel<<<dim3(Tt / 64, Hh, Bb), 128, FLASH_SMEM>>>(qkv, y);

    // GEMM2: out = y @ W_proj + b_proj  (fp32 out, final)
    h_gemm_kernel<float><<<dim3(Cc / 128, M / 128), 128, GEMM_SMEM>>>(y, wph, bp, out, M, Cc, Cc);
}